// round 2
// baseline (speedup 1.0000x reference)
#include <cuda_runtime.h>
#include <cuda_fp16.h>
#include <cstdint>

namespace {

constexpr int Bb = 4, Ss = 2048, Hh = 16, Dd = 128;
constexpr int BM = 128;              // query rows per CTA
constexpr int BN = 64;               // keys per tile
constexpr int NW = 8;                // warps per CTA
constexpr int NT = NW * 32;          // 256 threads
constexpr int KSTR = Dd + 8;         // smem row stride in halves (272B: conflict-free ldmatrix)
constexpr int NQT = Ss / BM;         // 16 query tiles per (b,h)
constexpr int TSTRIDE = 3 * Hh * Dd; // qkv stride per token (floats)
constexpr int SMEM_BYTES = (BM + 2 * BN) * KSTR * (int)sizeof(__half); // 69632
constexpr float SCALE = 0.08838834764831845f; // 1/sqrt(128)

__device__ __forceinline__ uint32_t cvta_s(const void* p) {
  return (uint32_t)__cvta_generic_to_shared(p);
}

__device__ __forceinline__ void ldm_x4(uint32_t& r0, uint32_t& r1, uint32_t& r2,
                                       uint32_t& r3, uint32_t a) {
  asm volatile("ldmatrix.sync.aligned.m8n8.x4.shared.b16 {%0,%1,%2,%3}, [%4];"
               : "=r"(r0), "=r"(r1), "=r"(r2), "=r"(r3) : "r"(a));
}

__device__ __forceinline__ void ldm_x4_t(uint32_t& r0, uint32_t& r1, uint32_t& r2,
                                         uint32_t& r3, uint32_t a) {
  asm volatile("ldmatrix.sync.aligned.m8n8.x4.trans.shared.b16 {%0,%1,%2,%3}, [%4];"
               : "=r"(r0), "=r"(r1), "=r"(r2), "=r"(r3) : "r"(a));
}

__device__ __forceinline__ void mma16816(float* c, uint32_t a0, uint32_t a1,
                                         uint32_t a2, uint32_t a3,
                                         uint32_t b0, uint32_t b1) {
  asm volatile(
      "mma.sync.aligned.m16n8k16.row.col.f32.f16.f16.f32 "
      "{%0,%1,%2,%3}, {%4,%5,%6,%7}, {%8,%9}, {%0,%1,%2,%3};"
      : "+f"(c[0]), "+f"(c[1]), "+f"(c[2]), "+f"(c[3])
      : "r"(a0), "r"(a1), "r"(a2), "r"(a3), "r"(b0), "r"(b1));
}

__device__ __forceinline__ uint32_t packh2(float x, float y) {
  __half2 h = __floats2half2_rn(x, y);
  return *reinterpret_cast<uint32_t*>(&h);
}

} // namespace

extern __shared__ __half g_smem[];

__global__ void __launch_bounds__(NT, 1)
fa_fwd_kernel(const float* __restrict__ qkv, float* __restrict__ out) {
  __half* Qs = g_smem;               // [BM][KSTR]
  __half* Ks = Qs + BM * KSTR;       // [BN][KSTR]
  __half* Vs = Ks + BN * KSTR;       // [BN][KSTR]

  const int bid = blockIdx.x;
  const int qt = bid % NQT;
  const int bh = bid / NQT;
  const int b = bh / Hh;
  const int h = bh % Hh;
  const int q0 = qt * BM;

  const int tid = threadIdx.x;
  const int w = tid >> 5;
  const int lane = tid & 31;

  const float* qbase = qkv + ((size_t)b * Ss + q0) * TSTRIDE + (size_t)h * Dd;
  const float* kbase = qkv + (size_t)b * Ss * TSTRIDE + (size_t)(1 * Hh + h) * Dd;
  const float* vbase = qkv + (size_t)b * Ss * TSTRIDE + (size_t)(2 * Hh + h) * Dd;

  // ---- load Q tile (fp32 -> fp16 in smem) ----
#pragma unroll 4
  for (int i = tid; i < BM * (Dd / 4); i += NT) {
    int r = i >> 5;
    int c = (i & 31) << 2;
    float4 f = *reinterpret_cast<const float4*>(qbase + (size_t)r * TSTRIDE + c);
    __half2* dq = reinterpret_cast<__half2*>(&Qs[r * KSTR + c]);
    dq[0] = __floats2half2_rn(f.x, f.y);
    dq[1] = __floats2half2_rn(f.z, f.w);
  }

  // ---- per-warp state ----
  float oacc[16][4];
#pragma unroll
  for (int i = 0; i < 16; i++)
#pragma unroll
    for (int j = 0; j < 4; j++) oacc[i][j] = 0.f;
  float m0s = -1e30f, m1s = -1e30f; // running max (rows m, m+8)
  float l0s = 0.f, l1s = 0.f;       // per-thread partial row sums

  const int qw = q0 + w * 16; // first global query row of this warp

  const uint32_t qs_base = cvta_s(Qs);
  const uint32_t ks_base = cvta_s(Ks);
  const uint32_t vs_base = cvta_s(Vs);

  // ldmatrix per-lane byte offsets
  const uint32_t a_off =
      ((uint32_t)((w * 16 + (lane & 15)) * KSTR + ((lane >> 4) << 3))) * 2u;
  const uint32_t b_off =
      ((uint32_t)(((lane & 7) + ((lane >> 4) << 3)) * KSTR +
                  (((lane >> 3) & 1) << 3))) * 2u;
  const uint32_t v_off =
      ((uint32_t)(((lane & 7) + (((lane >> 3) & 1) << 3)) * KSTR +
                  ((lane >> 4) << 3))) * 2u;

  const int ntiles = (q0 + BM) / BN;

  for (int t = 0; t < ntiles; ++t) {
    const int kv0 = t * BN;
    __syncthreads(); // previous tile's compute done before overwrite
    // ---- load K,V tile ----
#pragma unroll 4
    for (int i = tid; i < BN * (Dd / 4); i += NT) {
      int r = i >> 5;
      int c = (i & 31) << 2;
      size_t goff = (size_t)(kv0 + r) * TSTRIDE + c;
      float4 fk = *reinterpret_cast<const float4*>(kbase + goff);
      float4 fv = *reinterpret_cast<const float4*>(vbase + goff);
      __half2* dk = reinterpret_cast<__half2*>(&Ks[r * KSTR + c]);
      dk[0] = __floats2half2_rn(fk.x, fk.y);
      dk[1] = __floats2half2_rn(fk.z, fk.w);
      __half2* dv = reinterpret_cast<__half2*>(&Vs[r * KSTR + c]);
      dv[0] = __floats2half2_rn(fv.x, fv.y);
      dv[1] = __floats2half2_rn(fv.z, fv.w);
    }
    __syncthreads();

    if (kv0 <= qw + 15) { // warp has at least one unmasked key in this tile
      // ---- S = Q K^T ----
      float sacc[8][4];
#pragma unroll
      for (int i = 0; i < 8; i++)
#pragma unroll
        for (int j = 0; j < 4; j++) sacc[i][j] = 0.f;

#pragma unroll
      for (int kk = 0; kk < 8; ++kk) {
        uint32_t a0, a1, a2, a3;
        ldm_x4(a0, a1, a2, a3, qs_base + a_off + kk * 32);
#pragma unroll
        for (int np = 0; np < 4; ++np) {
          uint32_t b0, b1, b2, b3;
          ldm_x4(b0, b1, b2, b3,
                 ks_base + b_off + np * (16 * KSTR * 2) + kk * 32);
          mma16816(sacc[2 * np], a0, a1, a2, a3, b0, b1);
          mma16816(sacc[2 * np + 1], a0, a1, a2, a3, b2, b3);
        }
      }

      // ---- scale + causal mask ----
#pragma unroll
      for (int i = 0; i < 8; i++)
#pragma unroll
        for (int j = 0; j < 4; j++) sacc[i][j] *= SCALE;

      if (kv0 + BN - 1 > qw) {
        const int mrow = qw + (lane >> 2);
#pragma unroll
        for (int i = 0; i < 8; i++) {
          int nb = kv0 + i * 8 + ((lane & 3) << 1);
#pragma unroll
          for (int j = 0; j < 4; j++) {
            int n = nb + (j & 1);
            int m = mrow + ((j >= 2) ? 8 : 0);
            if (n > m) sacc[i][j] = -1e30f;
          }
        }
      }

      // ---- online softmax ----
      float rm0 = -1e30f, rm1 = -1e30f;
#pragma unroll
      for (int i = 0; i < 8; i++) {
        rm0 = fmaxf(rm0, fmaxf(sacc[i][0], sacc[i][1]));
        rm1 = fmaxf(rm1, fmaxf(sacc[i][2], sacc[i][3]));
      }
      rm0 = fmaxf(rm0, __shfl_xor_sync(0xffffffffu, rm0, 1));
      rm0 = fmaxf(rm0, __shfl_xor_sync(0xffffffffu, rm0, 2));
      rm1 = fmaxf(rm1, __shfl_xor_sync(0xffffffffu, rm1, 1));
      rm1 = fmaxf(rm1, __shfl_xor_sync(0xffffffffu, rm1, 2));

      const float mn0 = fmaxf(m0s, rm0);
      const float mn1 = fmaxf(m1s, rm1);
      const float al0 = __expf(m0s - mn0);
      const float al1 = __expf(m1s - mn1);
      m0s = mn0;
      m1s = mn1;

      float rs0 = 0.f, rs1 = 0.f;
#pragma unroll
      for (int i = 0; i < 8; i++) {
        sacc[i][0] = __expf(sacc[i][0] - mn0);
        sacc[i][1] = __expf(sacc[i][1] - mn0);
        sacc[i][2] = __expf(sacc[i][2] - mn1);
        sacc[i][3] = __expf(sacc[i][3] - mn1);
        rs0 += sacc[i][0] + sacc[i][1];
        rs1 += sacc[i][2] + sacc[i][3];
      }
      l0s = l0s * al0 + rs0;
      l1s = l1s * al1 + rs1;

#pragma unroll
      for (int i = 0; i < 16; i++) {
        oacc[i][0] *= al0;
        oacc[i][1] *= al0;
        oacc[i][2] *= al1;
        oacc[i][3] *= al1;
      }

      // ---- O += P V ----
#pragma unroll
      for (int kc = 0; kc < 4; ++kc) {
        uint32_t pa0 = packh2(sacc[2 * kc][0], sacc[2 * kc][1]);
        uint32_t pa1 = packh2(sacc[2 * kc][2], sacc[2 * kc][3]);
        uint32_t pa2 = packh2(sacc[2 * kc + 1][0], sacc[2 * kc + 1][1]);
        uint32_t pa3 = packh2(sacc[2 * kc + 1][2], sacc[2 * kc + 1][3]);
#pragma unroll
        for (int dp = 0; dp < 8; ++dp) {
          uint32_t v0, v1, v2, v3;
          ldm_x4_t(v0, v1, v2, v3,
                   vs_base + v_off + kc * (16 * KSTR * 2) + dp * 32);
          mma16816(oacc[2 * dp], pa0, pa1, pa2, pa3, v0, v1);
          mma16816(oacc[2 * dp + 1], pa0, pa1, pa2, pa3, v2, v3);
        }
      }
    }
  }

  // ---- epilogue: normalize + store fp32 ----
  float l0 = l0s;
  l0 += __shfl_xor_sync(0xffffffffu, l0, 1);
  l0 += __shfl_xor_sync(0xffffffffu, l0, 2);
  float l1 = l1s;
  l1 += __shfl_xor_sync(0xffffffffu, l1, 1);
  l1 += __shfl_xor_sync(0xffffffffu, l1, 2);
  const float inv0 = 1.f / l0;
  const float inv1 = 1.f / l1;

  const int mrow = qw + (lane >> 2);
  float* orow0 = out + ((size_t)(b * Ss + mrow) * Hh + h) * Dd;
  float* orow1 = out + ((size_t)(b * Ss + mrow + 8) * Hh + h) * Dd;
#pragma unroll
  for (int dt = 0; dt < 16; ++dt) {
    int d = dt * 8 + ((lane & 3) << 1);
    float2 v0 = make_float2(oacc[dt][0] * inv0, oacc[dt][1] * inv0);
    float2 v1 = make_float2(oacc[dt][2] * inv1, oacc[dt][3] * inv1);
    *reinterpret_cast<float2*>(orow0 + d) = v0;
    *reinterpret_cast<float2*>(orow1 + d) = v1;
  }
}

extern "C" void kernel_launch(void* const* d_in, const int* in_sizes, int n_in,
                              void* d_out, int out_size) {
  (void)in_sizes; (void)n_in; (void)out_size;
  const float* qkv = (const float*)d_in[0];
  float* out = (float*)d_out;
  cudaFuncSetAttribute(fa_fwd_kernel,
                       cudaFuncAttributeMaxDynamicSharedMemorySize, SMEM_BYTES);
  fa_fwd_kernel<<<Bb * Hh * NQT, NT, SMEM_BYTES>>>(qkv, out);
}

// round 3
// speedup vs baseline: 1.0216x; 1.0216x over previous
#include <cuda_runtime.h>
#include <cuda_fp16.h>
#include <cstdint>

namespace {

constexpr int Bb = 4, Ss = 2048, Hh = 16, Dd = 128;
constexpr int BM = 128;              // query rows per CTA
constexpr int BN = 64;               // keys per tile
constexpr int NW = 8;                // warps per CTA
constexpr int NT = NW * 32;          // 256 threads
constexpr int KSTR = Dd + 8;         // smem row stride in halves
constexpr int NQT = Ss / BM;         // 16 query tiles per (b,h)
constexpr int TSTRIDE = 3 * Hh * Dd; // qkv stride per token (floats)
// Q + double-buffered K,V
constexpr int SMEM_BYTES = (BM + 4 * BN) * KSTR * (int)sizeof(__half); // 104448
constexpr float SCALE2 = 0.08838834764831845f * 1.4426950408889634f; // 1/sqrt(128)*log2(e)

__device__ __forceinline__ uint32_t cvta_s(const void* p) {
  return (uint32_t)__cvta_generic_to_shared(p);
}

__device__ __forceinline__ float ex2f(float x) {
  float y;
  asm("ex2.approx.f32 %0, %1;" : "=f"(y) : "f"(x));
  return y;
}

__device__ __forceinline__ void ldm_x4(uint32_t& r0, uint32_t& r1, uint32_t& r2,
                                       uint32_t& r3, uint32_t a) {
  asm volatile("ldmatrix.sync.aligned.m8n8.x4.shared.b16 {%0,%1,%2,%3}, [%4];"
               : "=r"(r0), "=r"(r1), "=r"(r2), "=r"(r3) : "r"(a));
}

__device__ __forceinline__ void ldm_x4_t(uint32_t& r0, uint32_t& r1, uint32_t& r2,
                                         uint32_t& r3, uint32_t a) {
  asm volatile("ldmatrix.sync.aligned.m8n8.x4.trans.shared.b16 {%0,%1,%2,%3}, [%4];"
               : "=r"(r0), "=r"(r1), "=r"(r2), "=r"(r3) : "r"(a));
}

__device__ __forceinline__ void mma16816(float* c, uint32_t a0, uint32_t a1,
                                         uint32_t a2, uint32_t a3,
                                         uint32_t b0, uint32_t b1) {
  asm volatile(
      "mma.sync.aligned.m16n8k16.row.col.f32.f16.f16.f32 "
      "{%0,%1,%2,%3}, {%4,%5,%6,%7}, {%8,%9}, {%0,%1,%2,%3};"
      : "+f"(c[0]), "+f"(c[1]), "+f"(c[2]), "+f"(c[3])
      : "r"(a0), "r"(a1), "r"(a2), "r"(a3), "r"(b0), "r"(b1));
}

__device__ __forceinline__ uint32_t packh2(float x, float y) {
  __half2 h = __floats2half2_rn(x, y);
  return *reinterpret_cast<uint32_t*>(&h);
}

// Issue 8 float4 global loads for one 64x128 tile (per-thread share).
__device__ __forceinline__ void tile_ldg(const float* __restrict__ base, int kv0,
                                         int tid, float4 r[8]) {
#pragma unroll
  for (int j = 0; j < 8; ++j) {
    int i = tid + j * NT;
    int row = i >> 5;
    int c = (i & 31) << 2;
    r[j] = *reinterpret_cast<const float4*>(base + (size_t)(kv0 + row) * TSTRIDE + c);
  }
}

// Convert + store the per-thread share into an fp16 smem tile.
__device__ __forceinline__ void tile_sts(__half* __restrict__ dst, int tid,
                                         const float4 r[8]) {
#pragma unroll
  for (int j = 0; j < 8; ++j) {
    int i = tid + j * NT;
    int row = i >> 5;
    int c = (i & 31) << 2;
    __half2* d = reinterpret_cast<__half2*>(&dst[row * KSTR + c]);
    d[0] = __floats2half2_rn(r[j].x, r[j].y);
    d[1] = __floats2half2_rn(r[j].z, r[j].w);
  }
}

} // namespace

extern __shared__ __half g_smem[];

__global__ void __launch_bounds__(NT, 1)
fa_fwd_kernel(const float* __restrict__ qkv, float* __restrict__ out) {
  __half* Qs = g_smem;                    // [BM][KSTR]
  __half* Ksb[2] = {Qs + BM * KSTR, Qs + (BM + 2 * BN) * KSTR};
  __half* Vsb[2] = {Ksb[0] + BN * KSTR, Ksb[1] + BN * KSTR};

  const int bid = blockIdx.x;
  const int qt = bid % NQT;
  const int bh = bid / NQT;
  const int b = bh / Hh;
  const int h = bh % Hh;
  const int q0 = qt * BM;

  const int tid = threadIdx.x;
  const int w = tid >> 5;
  const int lane = tid & 31;

  const float* qbase = qkv + ((size_t)b * Ss + q0) * TSTRIDE + (size_t)h * Dd;
  const float* kbase = qkv + (size_t)b * Ss * TSTRIDE + (size_t)(1 * Hh + h) * Dd;
  const float* vbase = qkv + (size_t)b * Ss * TSTRIDE + (size_t)(2 * Hh + h) * Dd;

  // ---- prologue: load Q tile + K/V tile 0 ----
  float4 kr[8], vr[8];
  tile_ldg(kbase, 0, tid, kr);
  tile_ldg(vbase, 0, tid, vr);

#pragma unroll 4
  for (int i = tid; i < BM * (Dd / 4); i += NT) {
    int r = i >> 5;
    int c = (i & 31) << 2;
    float4 f = *reinterpret_cast<const float4*>(qbase + (size_t)r * TSTRIDE + c);
    __half2* dq = reinterpret_cast<__half2*>(&Qs[r * KSTR + c]);
    dq[0] = __floats2half2_rn(f.x, f.y);
    dq[1] = __floats2half2_rn(f.z, f.w);
  }
  tile_sts(Ksb[0], tid, kr);
  tile_sts(Vsb[0], tid, vr);
  __syncthreads();

  // ---- per-warp state ----
  float oacc[16][4];
#pragma unroll
  for (int i = 0; i < 16; i++)
#pragma unroll
    for (int j = 0; j < 4; j++) oacc[i][j] = 0.f;
  float m0s = -1e30f, m1s = -1e30f;
  float l0s = 0.f, l1s = 0.f;

  const int qw = q0 + w * 16;

  const uint32_t qs_base = cvta_s(Qs);

  const uint32_t a_off =
      ((uint32_t)((w * 16 + (lane & 15)) * KSTR + ((lane >> 4) << 3))) * 2u;
  const uint32_t b_off =
      ((uint32_t)(((lane & 7) + ((lane >> 4) << 3)) * KSTR +
                  (((lane >> 3) & 1) << 3))) * 2u;
  const uint32_t v_off =
      ((uint32_t)(((lane & 7) + (((lane >> 3) & 1) << 3)) * KSTR +
                  ((lane >> 4) << 3))) * 2u;

  const int ntiles = (q0 + BM) / BN;

  for (int t = 0; t < ntiles; ++t) {
    const int kv0 = t * BN;
    const int cur = t & 1;
    const int nxt = cur ^ 1;
    const bool hasnext = (t + 1) < ntiles;
    const bool active = kv0 <= qw + 15;

    const uint32_t ks_base = cvta_s(Ksb[cur]);
    const uint32_t vs_base = cvta_s(Vsb[cur]);

    // prefetch next K tile (latency hidden under S = Q K^T)
    if (hasnext) tile_ldg(kbase, kv0 + BN, tid, kr);

    float sacc[8][4];
    if (active) {
      // ---- S = Q K^T ----
#pragma unroll
      for (int i = 0; i < 8; i++)
#pragma unroll
        for (int j = 0; j < 4; j++) sacc[i][j] = 0.f;

#pragma unroll
      for (int kk = 0; kk < 8; ++kk) {
        uint32_t a0, a1, a2, a3;
        ldm_x4(a0, a1, a2, a3, qs_base + a_off + kk * 32);
#pragma unroll
        for (int np = 0; np < 4; ++np) {
          uint32_t b0, b1, b2, b3;
          ldm_x4(b0, b1, b2, b3,
                 ks_base + b_off + np * (16 * KSTR * 2) + kk * 32);
          mma16816(sacc[2 * np], a0, a1, a2, a3, b0, b1);
          mma16816(sacc[2 * np + 1], a0, a1, a2, a3, b2, b3);
        }
      }
    }

    // drain K prefetch into the other buffer; start V prefetch
    if (hasnext) {
      tile_sts(Ksb[nxt], tid, kr);
      tile_ldg(vbase, kv0 + BN, tid, vr);
    }

    if (active) {
      // ---- scale (base-2) + causal mask ----
#pragma unroll
      for (int i = 0; i < 8; i++)
#pragma unroll
        for (int j = 0; j < 4; j++) sacc[i][j] *= SCALE2;

      if (kv0 + BN - 1 > qw) {
        const int mrow = qw + (lane >> 2);
#pragma unroll
        for (int i = 0; i < 8; i++) {
          int nb = kv0 + i * 8 + ((lane & 3) << 1);
#pragma unroll
          for (int j = 0; j < 4; j++) {
            int n = nb + (j & 1);
            int m = mrow + ((j >= 2) ? 8 : 0);
            if (n > m) sacc[i][j] = -1e30f;
          }
        }
      }

      // ---- online softmax (base-2) ----
      float rm0 = -1e30f, rm1 = -1e30f;
#pragma unroll
      for (int i = 0; i < 8; i++) {
        rm0 = fmaxf(rm0, fmaxf(sacc[i][0], sacc[i][1]));
        rm1 = fmaxf(rm1, fmaxf(sacc[i][2], sacc[i][3]));
      }
      rm0 = fmaxf(rm0, __shfl_xor_sync(0xffffffffu, rm0, 1));
      rm0 = fmaxf(rm0, __shfl_xor_sync(0xffffffffu, rm0, 2));
      rm1 = fmaxf(rm1, __shfl_xor_sync(0xffffffffu, rm1, 1));
      rm1 = fmaxf(rm1, __shfl_xor_sync(0xffffffffu, rm1, 2));

      const float mn0 = fmaxf(m0s, rm0);
      const float mn1 = fmaxf(m1s, rm1);
      const float al0 = ex2f(m0s - mn0);
      const float al1 = ex2f(m1s - mn1);
      m0s = mn0;
      m1s = mn1;

      float rs0 = 0.f, rs1 = 0.f;
#pragma unroll
      for (int i = 0; i < 8; i++) {
        sacc[i][0] = ex2f(sacc[i][0] - mn0);
        sacc[i][1] = ex2f(sacc[i][1] - mn0);
        sacc[i][2] = ex2f(sacc[i][2] - mn1);
        sacc[i][3] = ex2f(sacc[i][3] - mn1);
        rs0 += sacc[i][0] + sacc[i][1];
        rs1 += sacc[i][2] + sacc[i][3];
      }
      l0s = l0s * al0 + rs0;
      l1s = l1s * al1 + rs1;

#pragma unroll
      for (int i = 0; i < 16; i++) {
        oacc[i][0] *= al0;
        oacc[i][1] *= al0;
        oacc[i][2] *= al1;
        oacc[i][3] *= al1;
      }
    }

    // drain V prefetch
    if (hasnext) tile_sts(Vsb[nxt], tid, vr);

    if (active) {
      // ---- O += P V ----
#pragma unroll
      for (int kc = 0; kc < 4; ++kc) {
        uint32_t pa0 = packh2(sacc[2 * kc][0], sacc[2 * kc][1]);
        uint32_t pa1 = packh2(sacc[2 * kc][2], sacc[2 * kc][3]);
        uint32_t pa2 = packh2(sacc[2 * kc + 1][0], sacc[2 * kc + 1][1]);
        uint32_t pa3 = packh2(sacc[2 * kc + 1][2], sacc[2 * kc + 1][3]);
#pragma unroll
        for (int dp = 0; dp < 8; ++dp) {
          uint32_t v0, v1, v2, v3;
          ldm_x4_t(v0, v1, v2, v3,
                   vs_base + v_off + kc * (16 * KSTR * 2) + dp * 32);
          mma16816(oacc[2 * dp], pa0, pa1, pa2, pa3, v0, v1);
          mma16816(oacc[2 * dp + 1], pa0, pa1, pa2, pa3, v2, v3);
        }
      }
    }
    __syncthreads();
  }

  // ---- epilogue: normalize + store fp32 ----
  float l0 = l0s;
  l0 += __shfl_xor_sync(0xffffffffu, l0, 1);
  l0 += __shfl_xor_sync(0xffffffffu, l0, 2);
  float l1 = l1s;
  l1 += __shfl_xor_sync(0xffffffffu, l1, 1);
  l1 += __shfl_xor_sync(0xffffffffu, l1, 2);
  const float inv0 = 1.f / l0;
  const float inv1 = 1.f / l1;

  const int mrow = qw + (lane >> 2);
  float* orow0 = out + ((size_t)(b * Ss + mrow) * Hh + h) * Dd;
  float* orow1 = out + ((size_t)(b * Ss + mrow + 8) * Hh + h) * Dd;
#pragma unroll
  for (int dt = 0; dt < 16; ++dt) {
    int d = dt * 8 + ((lane & 3) << 1);
    float2 v0 = make_float2(oacc[dt][0] * inv0, oacc[dt][1] * inv0);
    float2 v1 = make_float2(oacc[dt][2] * inv1, oacc[dt][3] * inv1);
    *reinterpret_cast<float2*>(orow0 + d) = v0;
    *reinterpret_cast<float2*>(orow1 + d) = v1;
  }
}

extern "C" void kernel_launch(void* const* d_in, const int* in_sizes, int n_in,
                              void* d_out, int out_size) {
  (void)in_sizes; (void)n_in; (void)out_size;
  const float* qkv = (const float*)d_in[0];
  float* out = (float*)d_out;
  cudaFuncSetAttribute(fa_fwd_kernel,
                       cudaFuncAttributeMaxDynamicSharedMemorySize, SMEM_BYTES);
  fa_fwd_kernel<<<Bb * Hh * NQT, NT, SMEM_BYTES>>>(qkv, out);
}

// round 4
// speedup vs baseline: 1.1420x; 1.1178x over previous
#include <cuda_runtime.h>
#include <cuda_fp16.h>
#include <cstdint>

namespace {

constexpr int Bb = 4, Ss = 2048, Hh = 16, Dd = 128;
constexpr int BM = 64;               // query rows per CTA
constexpr int BN = 64;               // keys per tile
constexpr int NW = 4;                // warps per CTA
constexpr int NT = NW * 32;          // 128 threads
constexpr int KSTR = Dd + 8;         // smem row stride in halves (272B)
constexpr int NQT = Ss / BM;         // 32 query tiles per (b,h)
constexpr int TSTRIDE = 3 * Hh * Dd; // qkv stride per token (floats)
constexpr int SMEM_BYTES = (BM + 2 * BN) * KSTR * (int)sizeof(__half); // 52224
constexpr float SCALE2 = 0.08838834764831845f * 1.4426950408889634f; // 1/sqrt(128)*log2e

__device__ __forceinline__ uint32_t cvta_s(const void* p) {
  return (uint32_t)__cvta_generic_to_shared(p);
}

__device__ __forceinline__ float ex2f(float x) {
  float y;
  asm("ex2.approx.f32 %0, %1;" : "=f"(y) : "f"(x));
  return y;
}

__device__ __forceinline__ void ldm_x4(uint32_t& r0, uint32_t& r1, uint32_t& r2,
                                       uint32_t& r3, uint32_t a) {
  asm volatile("ldmatrix.sync.aligned.m8n8.x4.shared.b16 {%0,%1,%2,%3}, [%4];"
               : "=r"(r0), "=r"(r1), "=r"(r2), "=r"(r3) : "r"(a));
}

__device__ __forceinline__ void ldm_x4_t(uint32_t& r0, uint32_t& r1, uint32_t& r2,
                                         uint32_t& r3, uint32_t a) {
  asm volatile("ldmatrix.sync.aligned.m8n8.x4.trans.shared.b16 {%0,%1,%2,%3}, [%4];"
               : "=r"(r0), "=r"(r1), "=r"(r2), "=r"(r3) : "r"(a));
}

__device__ __forceinline__ void mma16816(float* c, uint32_t a0, uint32_t a1,
                                         uint32_t a2, uint32_t a3,
                                         uint32_t b0, uint32_t b1) {
  asm volatile(
      "mma.sync.aligned.m16n8k16.row.col.f32.f16.f16.f32 "
      "{%0,%1,%2,%3}, {%4,%5,%6,%7}, {%8,%9}, {%0,%1,%2,%3};"
      : "+f"(c[0]), "+f"(c[1]), "+f"(c[2]), "+f"(c[3])
      : "r"(a0), "r"(a1), "r"(a2), "r"(a3), "r"(b0), "r"(b1));
}

__device__ __forceinline__ uint32_t packh2(float x, float y) {
  __half2 h = __floats2half2_rn(x, y);
  return *reinterpret_cast<uint32_t*>(&h);
}

} // namespace

extern __shared__ __half g_smem[];

__global__ void __launch_bounds__(NT, 3)
fa_fwd_kernel(const float* __restrict__ qkv, float* __restrict__ out) {
  __half* Qs = g_smem;               // [BM][KSTR]
  __half* Ks = Qs + BM * KSTR;       // [BN][KSTR]
  __half* Vs = Ks + BN * KSTR;       // [BN][KSTR]

  const int bid = blockIdx.x;
  const int qt = bid % NQT;
  const int bh = bid / NQT;
  const int b = bh / Hh;
  const int h = bh % Hh;
  const int q0 = qt * BM;

  const int tid = threadIdx.x;
  const int w = tid >> 5;
  const int lane = tid & 31;

  const float* qbase = qkv + ((size_t)b * Ss + q0) * TSTRIDE + (size_t)h * Dd;
  const float* kbase = qkv + (size_t)b * Ss * TSTRIDE + (size_t)(1 * Hh + h) * Dd;
  const float* vbase = qkv + (size_t)b * Ss * TSTRIDE + (size_t)(2 * Hh + h) * Dd;

  // ---- load Q tile (fp32 -> fp16 in smem) ----
#pragma unroll 4
  for (int i = tid; i < BM * (Dd / 4); i += NT) {
    int r = i >> 5;
    int c = (i & 31) << 2;
    float4 f = *reinterpret_cast<const float4*>(qbase + (size_t)r * TSTRIDE + c);
    __half2* dq = reinterpret_cast<__half2*>(&Qs[r * KSTR + c]);
    dq[0] = __floats2half2_rn(f.x, f.y);
    dq[1] = __floats2half2_rn(f.z, f.w);
  }

  // ---- per-warp state ----
  float oacc[16][4];
#pragma unroll
  for (int i = 0; i < 16; i++)
#pragma unroll
    for (int j = 0; j < 4; j++) oacc[i][j] = 0.f;
  float m0s = -1e30f, m1s = -1e30f;
  float l0s = 0.f, l1s = 0.f;

  const int qw = q0 + w * 16; // first global query row of this warp

  const uint32_t qs_base = cvta_s(Qs);
  const uint32_t ks_base = cvta_s(Ks);
  const uint32_t vs_base = cvta_s(Vs);

  const uint32_t a_off =
      ((uint32_t)((w * 16 + (lane & 15)) * KSTR + ((lane >> 4) << 3))) * 2u;
  const uint32_t b_off =
      ((uint32_t)(((lane & 7) + ((lane >> 4) << 3)) * KSTR +
                  (((lane >> 3) & 1) << 3))) * 2u;
  const uint32_t v_off =
      ((uint32_t)(((lane & 7) + (((lane >> 3) & 1) << 3)) * KSTR +
                  ((lane >> 4) << 3))) * 2u;

  const int ntiles = (q0 + BM) / BN; // last tile ends exactly at the diagonal

  for (int t = 0; t < ntiles; ++t) {
    const int kv0 = t * BN;
    __syncthreads(); // previous tile fully consumed before overwrite
    // ---- load K,V tile (fp32 -> fp16) ----
#pragma unroll 4
    for (int i = tid; i < BN * (Dd / 4); i += NT) {
      int r = i >> 5;
      int c = (i & 31) << 2;
      size_t goff = (size_t)(kv0 + r) * TSTRIDE + c;
      float4 fk = *reinterpret_cast<const float4*>(kbase + goff);
      float4 fv = *reinterpret_cast<const float4*>(vbase + goff);
      __half2* dk = reinterpret_cast<__half2*>(&Ks[r * KSTR + c]);
      dk[0] = __floats2half2_rn(fk.x, fk.y);
      dk[1] = __floats2half2_rn(fk.z, fk.w);
      __half2* dv = reinterpret_cast<__half2*>(&Vs[r * KSTR + c]);
      dv[0] = __floats2half2_rn(fv.x, fv.y);
      dv[1] = __floats2half2_rn(fv.z, fv.w);
    }
    __syncthreads();

    // ---- S = Q K^T ----
    float sacc[8][4];
#pragma unroll
    for (int i = 0; i < 8; i++)
#pragma unroll
      for (int j = 0; j < 4; j++) sacc[i][j] = 0.f;

#pragma unroll
    for (int kk = 0; kk < 8; ++kk) {
      uint32_t a0, a1, a2, a3;
      ldm_x4(a0, a1, a2, a3, qs_base + a_off + kk * 32);
#pragma unroll
      for (int np = 0; np < 4; ++np) {
        uint32_t b0, b1, b2, b3;
        ldm_x4(b0, b1, b2, b3,
               ks_base + b_off + np * (16 * KSTR * 2) + kk * 32);
        mma16816(sacc[2 * np], a0, a1, a2, a3, b0, b1);
        mma16816(sacc[2 * np + 1], a0, a1, a2, a3, b2, b3);
      }
    }

    // ---- scale (base-2) + causal mask (only final tile straddles diag) ----
#pragma unroll
    for (int i = 0; i < 8; i++)
#pragma unroll
      for (int j = 0; j < 4; j++) sacc[i][j] *= SCALE2;

    if (kv0 + BN - 1 > qw) {
      const int mrow = qw + (lane >> 2);
#pragma unroll
      for (int i = 0; i < 8; i++) {
        int nb = kv0 + i * 8 + ((lane & 3) << 1);
#pragma unroll
        for (int j = 0; j < 4; j++) {
          int n = nb + (j & 1);
          int m = mrow + ((j >= 2) ? 8 : 0);
          if (n > m) sacc[i][j] = -1e30f;
        }
      }
    }

    // ---- online softmax (base-2) ----
    float rm0 = -1e30f, rm1 = -1e30f;
#pragma unroll
    for (int i = 0; i < 8; i++) {
      rm0 = fmaxf(rm0, fmaxf(sacc[i][0], sacc[i][1]));
      rm1 = fmaxf(rm1, fmaxf(sacc[i][2], sacc[i][3]));
    }
    rm0 = fmaxf(rm0, __shfl_xor_sync(0xffffffffu, rm0, 1));
    rm0 = fmaxf(rm0, __shfl_xor_sync(0xffffffffu, rm0, 2));
    rm1 = fmaxf(rm1, __shfl_xor_sync(0xffffffffu, rm1, 1));
    rm1 = fmaxf(rm1, __shfl_xor_sync(0xffffffffu, rm1, 2));

    const float mn0 = fmaxf(m0s, rm0);
    const float mn1 = fmaxf(m1s, rm1);
    const float al0 = ex2f(m0s - mn0);
    const float al1 = ex2f(m1s - mn1);
    m0s = mn0;
    m1s = mn1;

    float rs0 = 0.f, rs1 = 0.f;
#pragma unroll
    for (int i = 0; i < 8; i++) {
      sacc[i][0] = ex2f(sacc[i][0] - mn0);
      sacc[i][1] = ex2f(sacc[i][1] - mn0);
      sacc[i][2] = ex2f(sacc[i][2] - mn1);
      sacc[i][3] = ex2f(sacc[i][3] - mn1);
      rs0 += sacc[i][0] + sacc[i][1];
      rs1 += sacc[i][2] + sacc[i][3];
    }
    l0s = l0s * al0 + rs0;
    l1s = l1s * al1 + rs1;

#pragma unroll
    for (int i = 0; i < 16; i++) {
      oacc[i][0] *= al0;
      oacc[i][1] *= al0;
      oacc[i][2] *= al1;
      oacc[i][3] *= al1;
    }

    // ---- O += P V ----
#pragma unroll
    for (int kc = 0; kc < 4; ++kc) {
      uint32_t pa0 = packh2(sacc[2 * kc][0], sacc[2 * kc][1]);
      uint32_t pa1 = packh2(sacc[2 * kc][2], sacc[2 * kc][3]);
      uint32_t pa2 = packh2(sacc[2 * kc + 1][0], sacc[2 * kc + 1][1]);
      uint32_t pa3 = packh2(sacc[2 * kc + 1][2], sacc[2 * kc + 1][3]);
#pragma unroll
      for (int dp = 0; dp < 8; ++dp) {
        uint32_t v0, v1, v2, v3;
        ldm_x4_t(v0, v1, v2, v3,
                 vs_base + v_off + kc * (16 * KSTR * 2) + dp * 32);
        mma16816(oacc[2 * dp], pa0, pa1, pa2, pa3, v0, v1);
        mma16816(oacc[2 * dp + 1], pa0, pa1, pa2, pa3, v2, v3);
      }
    }
  }

  // ---- epilogue: normalize + store fp32 ----
  float l0 = l0s;
  l0 += __shfl_xor_sync(0xffffffffu, l0, 1);
  l0 += __shfl_xor_sync(0xffffffffu, l0, 2);
  float l1 = l1s;
  l1 += __shfl_xor_sync(0xffffffffu, l1, 1);
  l1 += __shfl_xor_sync(0xffffffffu, l1, 2);
  const float inv0 = 1.f / l0;
  const float inv1 = 1.f / l1;

  const int mrow = qw + (lane >> 2);
  float* orow0 = out + ((size_t)(b * Ss + mrow) * Hh + h) * Dd;
  float* orow1 = out + ((size_t)(b * Ss + mrow + 8) * Hh + h) * Dd;
#pragma unroll
  for (int dt = 0; dt < 16; ++dt) {
    int d = dt * 8 + ((lane & 3) << 1);
    float2 v0 = make_float2(oacc[dt][0] * inv0, oacc[dt][1] * inv0);
    float2 v1 = make_float2(oacc[dt][2] * inv1, oacc[dt][3] * inv1);
    *reinterpret_cast<float2*>(orow0 + d) = v0;
    *reinterpret_cast<float2*>(orow1 + d) = v1;
  }
}

extern "C" void kernel_launch(void* const* d_in, const int* in_sizes, int n_in,
                              void* d_out, int out_size) {
  (void)in_sizes; (void)n_in; (void)out_size;
  const float* qkv = (const float*)d_in[0];
  float* out = (float*)d_out;
  cudaFuncSetAttribute(fa_fwd_kernel,
                       cudaFuncAttributeMaxDynamicSharedMemorySize, SMEM_BYTES);
  fa_fwd_kernel<<<Bb * Hh * NQT, NT, SMEM_BYTES>>>(qkv, out);
}

// round 7
// speedup vs baseline: 1.3343x; 1.1684x over previous
#include <cuda_runtime.h>
#include <cuda_fp16.h>
#include <cstdint>

namespace {

constexpr int Bb = 4, Ss = 2048, Hh = 16, Dd = 128;
constexpr int BM = 128;              // query rows per CTA
constexpr int BN = 64;               // keys per tile
constexpr int NT = 128;              // 4 warps, 32 query rows each
constexpr int KSTR = 136;            // smem row stride in halves (272B)
constexpr int NQT = Ss / BM;         // 16 query tiles per (b,h)
constexpr int TSTRIDE = 3 * Hh * Dd; // qkv token stride (floats)
constexpr int QBYTES = BM * KSTR * 2;        // 34816
constexpr int STAGEB = BN * KSTR * 2;        // 17408 per K or V stage
constexpr int SMEM_BYTES = QBYTES + 4 * STAGEB; // Q + 2x(K,V) = 104448
constexpr float SCALE2 = 0.08838834764831845f * 1.4426950408889634f; // 1/sqrt(d)*log2e
constexpr int KVN = Bb * Hh * Ss * Dd;       // 16.78M halves per tensor

__device__ __forceinline__ uint32_t cvta_s(const void* p) {
  return (uint32_t)__cvta_generic_to_shared(p);
}

__device__ __forceinline__ float ex2f(float x) {
  float y;
  asm("ex2.approx.f32 %0, %1;" : "=f"(y) : "f"(x));
  return y;
}

__device__ __forceinline__ void ldm_x4(uint32_t& r0, uint32_t& r1, uint32_t& r2,
                                       uint32_t& r3, uint32_t a) {
  asm volatile("ldmatrix.sync.aligned.m8n8.x4.shared.b16 {%0,%1,%2,%3}, [%4];"
               : "=r"(r0), "=r"(r1), "=r"(r2), "=r"(r3) : "r"(a));
}

__device__ __forceinline__ void ldm_x4_t(uint32_t& r0, uint32_t& r1, uint32_t& r2,
                                         uint32_t& r3, uint32_t a) {
  asm volatile("ldmatrix.sync.aligned.m8n8.x4.trans.shared.b16 {%0,%1,%2,%3}, [%4];"
               : "=r"(r0), "=r"(r1), "=r"(r2), "=r"(r3) : "r"(a));
}

__device__ __forceinline__ void mma16816(float* c, uint32_t a0, uint32_t a1,
                                         uint32_t a2, uint32_t a3,
                                         uint32_t b0, uint32_t b1) {
  asm volatile(
      "mma.sync.aligned.m16n8k16.row.col.f32.f16.f16.f32 "
      "{%0,%1,%2,%3}, {%4,%5,%6,%7}, {%8,%9}, {%0,%1,%2,%3};"
      : "+f"(c[0]), "+f"(c[1]), "+f"(c[2]), "+f"(c[3])
      : "r"(a0), "r"(a1), "r"(a2), "r"(a3), "r"(b0), "r"(b1));
}

__device__ __forceinline__ uint32_t packh2(float x, float y) {
  __half2 h = __floats2half2_rn(x, y);
  return *reinterpret_cast<uint32_t*>(&h);
}

__device__ __forceinline__ void cp16(uint32_t saddr, const void* gaddr) {
  asm volatile("cp.async.cg.shared.global [%0], [%1], 16;" ::
               "r"(saddr), "l"(gaddr));
}

#define CP_COMMIT() asm volatile("cp.async.commit_group;" ::: "memory")
#define CP_WAIT(N) asm volatile("cp.async.wait_group %0;" :: "n"(N) : "memory")

} // namespace

// fp16 K/V scratch, head-major [b][h][s][d]
__device__ __half g_Kh[KVN];
__device__ __half g_Vh[KVN];

// ---------------- prepass: fp32 [b,s,{K,V},h,d] -> fp16 [b,h,s,d] ----------------
__global__ void __launch_bounds__(256)
convert_kv(const float* __restrict__ qkv) {
  int i = blockIdx.x * 256 + threadIdx.x; // one float4 per thread
  if (i >= Bb * Ss * 2 * Hh * (Dd / 4)) return;
  int d4 = i & 31;
  int r = i >> 5;
  int h = r & (Hh - 1); r >>= 4;
  int c = r & 1;        r >>= 1;   // 0=K, 1=V
  int s = r & (Ss - 1);
  int b = r >> 11;
  const float4 f = *reinterpret_cast<const float4*>(
      qkv + (((size_t)(b * Ss + s) * 3 + (c + 1)) * Hh + h) * Dd + d4 * 4);
  uint2 v;
  v.x = packh2(f.x, f.y);
  v.y = packh2(f.z, f.w);
  __half* dst = (c ? g_Vh : g_Kh) + ((size_t)(b * Hh + h) * Ss + s) * Dd + d4 * 4;
  *reinterpret_cast<uint2*>(dst) = v;
}

// ---------------- main attention kernel ----------------
extern __shared__ char g_smem[];

__global__ void __launch_bounds__(NT, 2)
fa_fwd2(const float* __restrict__ qkv, float* __restrict__ out) {
  const uint32_t sb = cvta_s(g_smem);
  const int tid = threadIdx.x;
  const int w = tid >> 5;
  const int lane = tid & 31;

  const int bid = blockIdx.x;
  const int qt = bid % NQT;
  const int bh = bid / NQT;
  const int b = bh / Hh;
  const int h = bh % Hh;
  const int q0 = qt * BM;

  const __half* kg = g_Kh + (size_t)bh * Ss * Dd;
  const __half* vg = g_Vh + (size_t)bh * Ss * Dd;
  const float* qbase = qkv + ((size_t)b * Ss + q0) * TSTRIDE + (size_t)h * Dd;

  const uint32_t qsb = sb;                 // Q: 128 x 136 halves
  const uint32_t st0 = sb + QBYTES;        // [K0][V0][K1][V1]

  const int ntiles = (q0 + BM) / BN;

  // ---- issue cp.async for K/V stage 0 ----
  {
    uint32_t ks = st0, vs = st0 + STAGEB;
#pragma unroll
    for (int j = 0; j < 8; ++j) {
      int idx = tid + j * NT;
      int row = idx >> 4, ch = idx & 15;
      uint32_t so = (uint32_t)(row * KSTR + ch * 8) * 2;
      cp16(ks + so, kg + (size_t)row * Dd + ch * 8);
      cp16(vs + so, vg + (size_t)row * Dd + ch * 8);
    }
    CP_COMMIT();
  }

  // ---- load Q (fp32 -> fp16, scale folded in) while stage0 is in flight ----
#pragma unroll 4
  for (int i = tid; i < BM * (Dd / 4); i += NT) {
    int row = i >> 5;
    int c = (i & 31) << 2;
    float4 f = *reinterpret_cast<const float4*>(qbase + (size_t)row * TSTRIDE + c);
    __half2* dq = reinterpret_cast<__half2*>(g_smem + (row * KSTR + c) * 2);
    dq[0] = __floats2half2_rn(f.x * SCALE2, f.y * SCALE2);
    dq[1] = __floats2half2_rn(f.z * SCALE2, f.w * SCALE2);
  }

  // ---- per-warp state ----
  float oacc[2][16][4];
#pragma unroll
  for (int s2 = 0; s2 < 2; s2++)
#pragma unroll
    for (int i = 0; i < 16; i++)
#pragma unroll
      for (int j = 0; j < 4; j++) oacc[s2][i][j] = 0.f;
  float lsum[2][2] = {{0.f, 0.f}, {0.f, 0.f}};

  const int qw = q0 + w * 32; // first query row of this warp (32 rows)

  const uint32_t a_off0 =
      ((uint32_t)((w * 32 + (lane & 15)) * KSTR + ((lane >> 4) << 3))) * 2u;
  const uint32_t a_off1 = a_off0 + (uint32_t)(16 * KSTR * 2);
  const uint32_t b_off =
      ((uint32_t)(((lane & 7) + ((lane >> 4) << 3)) * KSTR +
                  (((lane >> 3) & 1) << 3))) * 2u;
  const uint32_t v_off =
      ((uint32_t)(((lane & 7) + (((lane >> 3) & 1) << 3)) * KSTR +
                  ((lane >> 4) << 3))) * 2u;

  for (int t = 0; t < ntiles; ++t) {
    const int kv0 = t * BN;
    const bool hasnext = (t + 1) < ntiles;

    if (hasnext) { // prefetch stage t+1 into the other buffer
      uint32_t base = st0 + ((t + 1) & 1) * 2 * STAGEB;
      uint32_t ks = base, vs = base + STAGEB;
      const __half* kgn = kg + (size_t)(kv0 + BN) * Dd;
      const __half* vgn = vg + (size_t)(kv0 + BN) * Dd;
#pragma unroll
      for (int j = 0; j < 8; ++j) {
        int idx = tid + j * NT;
        int row = idx >> 4, ch = idx & 15;
        uint32_t so = (uint32_t)(row * KSTR + ch * 8) * 2;
        cp16(ks + so, kgn + (size_t)row * Dd + ch * 8);
        cp16(vs + so, vgn + (size_t)row * Dd + ch * 8);
      }
      CP_COMMIT();
      CP_WAIT(1); // stage t complete; t+1 still in flight
    } else {
      CP_WAIT(0);
    }
    __syncthreads();

    const uint32_t ks_base = st0 + (t & 1) * 2 * STAGEB;
    const uint32_t vs_base = ks_base + STAGEB;

    if (kv0 <= qw + 31) { // warp has unmasked keys in this tile
      // ---- S = Q K^T (two 16-row slabs) ----
      float sacc[2][8][4];
#pragma unroll
      for (int s2 = 0; s2 < 2; s2++)
#pragma unroll
        for (int i = 0; i < 8; i++)
#pragma unroll
          for (int j = 0; j < 4; j++) sacc[s2][i][j] = 0.f;

#pragma unroll
      for (int kk = 0; kk < 8; ++kk) {
        uint32_t a0[4], a1[4];
        ldm_x4(a0[0], a0[1], a0[2], a0[3], qsb + a_off0 + kk * 32);
        ldm_x4(a1[0], a1[1], a1[2], a1[3], qsb + a_off1 + kk * 32);
#pragma unroll
        for (int np = 0; np < 4; ++np) {
          uint32_t b0, b1, b2, b3;
          ldm_x4(b0, b1, b2, b3, ks_base + b_off + np * (16 * KSTR * 2) + kk * 32);
          mma16816(sacc[0][2 * np], a0[0], a0[1], a0[2], a0[3], b0, b1);
          mma16816(sacc[0][2 * np + 1], a0[0], a0[1], a0[2], a0[3], b2, b3);
          mma16816(sacc[1][2 * np], a1[0], a1[1], a1[2], a1[3], b0, b1);
          mma16816(sacc[1][2 * np + 1], a1[0], a1[1], a1[2], a1[3], b2, b3);
        }
      }

      // ---- exp2 + causal mask (no running max; scores bounded) ----
      const bool needmask = (kv0 + BN - 1) > qw;
#pragma unroll
      for (int s2 = 0; s2 < 2; s2++) {
        const int rbase = qw + s2 * 16 + (lane >> 2);
        float rs0 = 0.f, rs1 = 0.f;
#pragma unroll
        for (int i = 0; i < 8; i++) {
          float p0, p1, p2, p3;
          if (needmask) {
            int n0 = kv0 + i * 8 + ((lane & 3) << 1);
            p0 = (n0 > rbase) ? 0.f : ex2f(sacc[s2][i][0]);
            p1 = (n0 + 1 > rbase) ? 0.f : ex2f(sacc[s2][i][1]);
            p2 = (n0 > rbase + 8) ? 0.f : ex2f(sacc[s2][i][2]);
            p3 = (n0 + 1 > rbase + 8) ? 0.f : ex2f(sacc[s2][i][3]);
          } else {
            p0 = ex2f(sacc[s2][i][0]);
            p1 = ex2f(sacc[s2][i][1]);
            p2 = ex2f(sacc[s2][i][2]);
            p3 = ex2f(sacc[s2][i][3]);
          }
          rs0 += p0 + p1;
          rs1 += p2 + p3;
          sacc[s2][i][0] = p0;
          sacc[s2][i][1] = p1;
          sacc[s2][i][2] = p2;
          sacc[s2][i][3] = p3;
        }
        lsum[s2][0] += rs0;
        lsum[s2][1] += rs1;
      }

      // ---- pack P to fp16 fragments ----
      uint32_t preg[2][16];
#pragma unroll
      for (int s2 = 0; s2 < 2; s2++)
#pragma unroll
        for (int kc = 0; kc < 4; ++kc) {
          preg[s2][4 * kc + 0] = packh2(sacc[s2][2 * kc][0], sacc[s2][2 * kc][1]);
          preg[s2][4 * kc + 1] = packh2(sacc[s2][2 * kc][2], sacc[s2][2 * kc][3]);
          preg[s2][4 * kc + 2] = packh2(sacc[s2][2 * kc + 1][0], sacc[s2][2 * kc + 1][1]);
          preg[s2][4 * kc + 3] = packh2(sacc[s2][2 * kc + 1][2], sacc[s2][2 * kc + 1][3]);
        }

      // ---- O += P V (V fragments shared across both slabs) ----
#pragma unroll
      for (int kc = 0; kc < 4; ++kc) {
#pragma unroll
        for (int dp = 0; dp < 8; ++dp) {
          uint32_t v0, v1, v2, v3;
          ldm_x4_t(v0, v1, v2, v3,
                   vs_base + v_off + kc * (16 * KSTR * 2) + dp * 32);
          mma16816(oacc[0][2 * dp], preg[0][4 * kc + 0], preg[0][4 * kc + 1],
                   preg[0][4 * kc + 2], preg[0][4 * kc + 3], v0, v1);
          mma16816(oacc[0][2 * dp + 1], preg[0][4 * kc + 0], preg[0][4 * kc + 1],
                   preg[0][4 * kc + 2], preg[0][4 * kc + 3], v2, v3);
          mma16816(oacc[1][2 * dp], preg[1][4 * kc + 0], preg[1][4 * kc + 1],
                   preg[1][4 * kc + 2], preg[1][4 * kc + 3], v0, v1);
          mma16816(oacc[1][2 * dp + 1], preg[1][4 * kc + 0], preg[1][4 * kc + 1],
                   preg[1][4 * kc + 2], preg[1][4 * kc + 3], v2, v3);
        }
      }
    }
    __syncthreads();
  }

  // ---- epilogue: normalize + store ----
#pragma unroll
  for (int s2 = 0; s2 < 2; s2++)
#pragma unroll
    for (int hf = 0; hf < 2; hf++) {
      float l = lsum[s2][hf];
      l += __shfl_xor_sync(0xffffffffu, l, 1);
      l += __shfl_xor_sync(0xffffffffu, l, 2);
      const float inv = 1.f / l;
      const int row = qw + s2 * 16 + hf * 8 + (lane >> 2);
      float* orow = out + ((size_t)(b * Ss + row) * Hh + h) * Dd;
#pragma unroll
      for (int dt = 0; dt < 16; ++dt) {
        int d = dt * 8 + ((lane & 3) << 1);
        float2 v = make_float2(oacc[s2][dt][2 * hf] * inv,
                               oacc[s2][dt][2 * hf + 1] * inv);
        *reinterpret_cast<float2*>(orow + d) = v;
      }
    }
}

extern "C" void kernel_launch(void* const* d_in, const int* in_sizes, int n_in,
                              void* d_out, int out_size) {
  (void)in_sizes; (void)n_in; (void)out_size;
  const float* qkv = (const float*)d_in[0];
  float* out = (float*)d_out;

  int nconv = Bb * Ss * 2 * Hh * (Dd / 4);
  convert_kv<<<(nconv + 255) / 256, 256>>>(qkv);

  cudaFuncSetAttribute(fa_fwd2,
                       cudaFuncAttributeMaxDynamicSharedMemorySize, SMEM_BYTES);
  fa_fwd2<<<Bb * Hh * NQT, NT, SMEM_BYTES>>>(qkv, out);
}

// round 10
// speedup vs baseline: 1.3461x; 1.0088x over previous
#include <cuda_runtime.h>
#include <cuda_fp16.h>
#include <cstdint>

namespace {

constexpr int Bb = 4, Ss = 2048, Hh = 16, Dd = 128;
constexpr int BM = 128;              // query rows per CTA
constexpr int BN = 64;               // keys per tile
constexpr int NT = 128;              // 4 warps, 32 query rows each
constexpr int KSTR = 136;            // smem row stride in halves (272B)
constexpr int NQT = Ss / BM;         // 16 query tiles per (b,h)
constexpr int TSTRIDE = 3 * Hh * Dd; // qkv token stride (floats)
constexpr int QBYTES = BM * KSTR * 2;        // 34816
constexpr int STAGEB = BN * KSTR * 2;        // 17408 per K or V stage
constexpr int SMEM_BYTES = QBYTES + 4 * STAGEB; // Q + 2x(K,V) = 104448
constexpr float SCALE2 = 0.08838834764831845f * 1.4426950408889634f; // 1/sqrt(d)*log2e
constexpr int KVN = Bb * Hh * Ss * Dd;       // 16.78M halves per tensor

__device__ __forceinline__ uint32_t cvta_s(const void* p) {
  return (uint32_t)__cvta_generic_to_shared(p);
}

__device__ __forceinline__ float ex2f(float x) {
  float y;
  asm("ex2.approx.f32 %0, %1;" : "=f"(y) : "f"(x));
  return y;
}

__device__ __forceinline__ void ldm_x4(uint32_t& r0, uint32_t& r1, uint32_t& r2,
                                       uint32_t& r3, uint32_t a) {
  asm volatile("ldmatrix.sync.aligned.m8n8.x4.shared.b16 {%0,%1,%2,%3}, [%4];"
               : "=r"(r0), "=r"(r1), "=r"(r2), "=r"(r3) : "r"(a));
}

__device__ __forceinline__ void ldm_x4_t(uint32_t& r0, uint32_t& r1, uint32_t& r2,
                                         uint32_t& r3, uint32_t a) {
  asm volatile("ldmatrix.sync.aligned.m8n8.x4.trans.shared.b16 {%0,%1,%2,%3}, [%4];"
               : "=r"(r0), "=r"(r1), "=r"(r2), "=r"(r3) : "r"(a));
}

__device__ __forceinline__ void mma16816(float* c, uint32_t a0, uint32_t a1,
                                         uint32_t a2, uint32_t a3,
                                         uint32_t b0, uint32_t b1) {
  asm volatile(
      "mma.sync.aligned.m16n8k16.row.col.f32.f16.f16.f32 "
      "{%0,%1,%2,%3}, {%4,%5,%6,%7}, {%8,%9}, {%0,%1,%2,%3};"
      : "+f"(c[0]), "+f"(c[1]), "+f"(c[2]), "+f"(c[3])
      : "r"(a0), "r"(a1), "r"(a2), "r"(a3), "r"(b0), "r"(b1));
}

__device__ __forceinline__ uint32_t packh2(float x, float y) {
  __half2 h = __floats2half2_rn(x, y);
  return *reinterpret_cast<uint32_t*>(&h);
}

__device__ __forceinline__ void cp16(uint32_t saddr, const void* gaddr) {
  asm volatile("cp.async.cg.shared.global [%0], [%1], 16;" ::
               "r"(saddr), "l"(gaddr));
}

#define CP_COMMIT() asm volatile("cp.async.commit_group;" ::: "memory")
#define CP_WAIT(N) asm volatile("cp.async.wait_group %0;" :: "n"(N) : "memory")

} // namespace

// fp16 K/V scratch, head-major [b][h][s][d]
__device__ __half g_Kh[KVN];
__device__ __half g_Vh[KVN];

// ---------------- prepass: fp32 [b,s,{K,V},h,d] -> fp16 [b,h,s,d] ----------------
__global__ void __launch_bounds__(256)
convert_kv(const float* __restrict__ qkv) {
  int i = blockIdx.x * 256 + threadIdx.x; // one float4 per thread
  if (i >= Bb * Ss * 2 * Hh * (Dd / 4)) return;
  int d4 = i & 31;
  int r = i >> 5;
  int h = r & (Hh - 1); r >>= 4;
  int c = r & 1;        r >>= 1;   // 0=K, 1=V
  int s = r & (Ss - 1);
  int b = r >> 11;
  const float4 f = *reinterpret_cast<const float4*>(
      qkv + (((size_t)(b * Ss + s) * 3 + (c + 1)) * Hh + h) * Dd + d4 * 4);
  uint2 v;
  v.x = packh2(f.x, f.y);
  v.y = packh2(f.z, f.w);
  __half* dst = (c ? g_Vh : g_Kh) + ((size_t)(b * Hh + h) * Ss + s) * Dd + d4 * 4;
  *reinterpret_cast<uint2*>(dst) = v;
}

// ---------------- main attention kernel ----------------
extern __shared__ char g_smem[];

__global__ void __launch_bounds__(NT, 2)
fa_fwd2(const float* __restrict__ qkv, float* __restrict__ out) {
  const uint32_t sb = cvta_s(g_smem);
  const int tid = threadIdx.x;
  const int w = tid >> 5;
  const int lane = tid & 31;

  const int bid = blockIdx.x;
  const int qt = bid % NQT;
  const int bh = bid / NQT;
  const int b = bh / Hh;
  const int h = bh % Hh;
  const int q0 = qt * BM;

  const __half* kg = g_Kh + (size_t)bh * Ss * Dd;
  const __half* vg = g_Vh + (size_t)bh * Ss * Dd;
  const float* qbase = qkv + ((size_t)b * Ss + q0) * TSTRIDE + (size_t)h * Dd;

  const uint32_t qsb = sb;                 // Q: 128 x 136 halves
  const uint32_t st0 = sb + QBYTES;        // [K0][V0][K1][V1]

  const int ntiles = (q0 + BM) / BN;

  // ---- issue cp.async for K/V stage 0 ----
  {
    uint32_t ks = st0, vs = st0 + STAGEB;
#pragma unroll
    for (int j = 0; j < 8; ++j) {
      int idx = tid + j * NT;
      int row = idx >> 4, ch = idx & 15;
      uint32_t so = (uint32_t)(row * KSTR + ch * 8) * 2;
      cp16(ks + so, kg + (size_t)row * Dd + ch * 8);
      cp16(vs + so, vg + (size_t)row * Dd + ch * 8);
    }
    CP_COMMIT();
  }

  // ---- load Q (fp32 -> fp16, scale folded in) while stage0 is in flight ----
#pragma unroll 4
  for (int i = tid; i < BM * (Dd / 4); i += NT) {
    int row = i >> 5;
    int c = (i & 31) << 2;
    float4 f = *reinterpret_cast<const float4*>(qbase + (size_t)row * TSTRIDE + c);
    __half2* dq = reinterpret_cast<__half2*>(g_smem + (row * KSTR + c) * 2);
    dq[0] = __floats2half2_rn(f.x * SCALE2, f.y * SCALE2);
    dq[1] = __floats2half2_rn(f.z * SCALE2, f.w * SCALE2);
  }

  // ---- per-warp state ----
  float oacc[2][16][4];
#pragma unroll
  for (int s2 = 0; s2 < 2; s2++)
#pragma unroll
    for (int i = 0; i < 16; i++)
#pragma unroll
      for (int j = 0; j < 4; j++) oacc[s2][i][j] = 0.f;
  float lsum[2][2] = {{0.f, 0.f}, {0.f, 0.f}};

  const int qw = q0 + w * 32; // first query row of this warp (32 rows)

  const uint32_t a_off0 =
      ((uint32_t)((w * 32 + (lane & 15)) * KSTR + ((lane >> 4) << 3))) * 2u;
  const uint32_t a_off1 = a_off0 + (uint32_t)(16 * KSTR * 2);
  const uint32_t b_off =
      ((uint32_t)(((lane & 7) + ((lane >> 4) << 3)) * KSTR +
                  (((lane >> 3) & 1) << 3))) * 2u;
  const uint32_t v_off =
      ((uint32_t)(((lane & 7) + (((lane >> 3) & 1) << 3)) * KSTR +
                  ((lane >> 4) << 3))) * 2u;

  for (int t = 0; t < ntiles; ++t) {
    const int kv0 = t * BN;
    const bool hasnext = (t + 1) < ntiles;

    if (hasnext) { // prefetch stage t+1 into the other buffer
      uint32_t base = st0 + ((t + 1) & 1) * 2 * STAGEB;
      uint32_t ks = base, vs = base + STAGEB;
      const __half* kgn = kg + (size_t)(kv0 + BN) * Dd;
      const __half* vgn = vg + (size_t)(kv0 + BN) * Dd;
#pragma unroll
      for (int j = 0; j < 8; ++j) {
        int idx = tid + j * NT;
        int row = idx >> 4, ch = idx & 15;
        uint32_t so = (uint32_t)(row * KSTR + ch * 8) * 2;
        cp16(ks + so, kgn + (size_t)row * Dd + ch * 8);
        cp16(vs + so, vgn + (size_t)row * Dd + ch * 8);
      }
      CP_COMMIT();
      CP_WAIT(1); // stage t complete; t+1 still in flight
    } else {
      CP_WAIT(0);
    }
    __syncthreads();

    const uint32_t ks_base = st0 + (t & 1) * 2 * STAGEB;
    const uint32_t vs_base = ks_base + STAGEB;

    if (kv0 <= qw + 31) { // warp has unmasked keys in this tile
      // ---- S = Q K^T (two 16-row slabs) ----
      float sacc[2][8][4];
#pragma unroll
      for (int s2 = 0; s2 < 2; s2++)
#pragma unroll
        for (int i = 0; i < 8; i++)
#pragma unroll
          for (int j = 0; j < 4; j++) sacc[s2][i][j] = 0.f;

#pragma unroll
      for (int kk = 0; kk < 8; ++kk) {
        uint32_t a0[4], a1[4];
        ldm_x4(a0[0], a0[1], a0[2], a0[3], qsb + a_off0 + kk * 32);
        ldm_x4(a1[0], a1[1], a1[2], a1[3], qsb + a_off1 + kk * 32);
#pragma unroll
        for (int np = 0; np < 4; ++np) {
          uint32_t b0, b1, b2, b3;
          ldm_x4(b0, b1, b2, b3, ks_base + b_off + np * (16 * KSTR * 2) + kk * 32);
          mma16816(sacc[0][2 * np], a0[0], a0[1], a0[2], a0[3], b0, b1);
          mma16816(sacc[0][2 * np + 1], a0[0], a0[1], a0[2], a0[3], b2, b3);
          mma16816(sacc[1][2 * np], a1[0], a1[1], a1[2], a1[3], b0, b1);
          mma16816(sacc[1][2 * np + 1], a1[0], a1[1], a1[2], a1[3], b2, b3);
        }
      }

      // ---- fused exp2 + causal mask + fp16 pack (sacc dies here; no write-back) ----
      const bool needmask = (kv0 + BN - 1) > qw;
      uint32_t preg[2][16];
#pragma unroll
      for (int s2 = 0; s2 < 2; s2++) {
        const int rbase = qw + s2 * 16 + (lane >> 2);
        float rs0 = 0.f, rs1 = 0.f;
#pragma unroll
        for (int kc = 0; kc < 4; ++kc) {
          float e0, e1, e2, e3, f0, f1, f2, f3;
          if (needmask) {
            int na = kv0 + (2 * kc) * 8 + ((lane & 3) << 1);
            int nb = na + 8;
            e0 = (na > rbase) ? 0.f : ex2f(sacc[s2][2 * kc][0]);
            e1 = (na + 1 > rbase) ? 0.f : ex2f(sacc[s2][2 * kc][1]);
            e2 = (na > rbase + 8) ? 0.f : ex2f(sacc[s2][2 * kc][2]);
            e3 = (na + 1 > rbase + 8) ? 0.f : ex2f(sacc[s2][2 * kc][3]);
            f0 = (nb > rbase) ? 0.f : ex2f(sacc[s2][2 * kc + 1][0]);
            f1 = (nb + 1 > rbase) ? 0.f : ex2f(sacc[s2][2 * kc + 1][1]);
            f2 = (nb > rbase + 8) ? 0.f : ex2f(sacc[s2][2 * kc + 1][2]);
            f3 = (nb + 1 > rbase + 8) ? 0.f : ex2f(sacc[s2][2 * kc + 1][3]);
          } else {
            e0 = ex2f(sacc[s2][2 * kc][0]);
            e1 = ex2f(sacc[s2][2 * kc][1]);
            e2 = ex2f(sacc[s2][2 * kc][2]);
            e3 = ex2f(sacc[s2][2 * kc][3]);
            f0 = ex2f(sacc[s2][2 * kc + 1][0]);
            f1 = ex2f(sacc[s2][2 * kc + 1][1]);
            f2 = ex2f(sacc[s2][2 * kc + 1][2]);
            f3 = ex2f(sacc[s2][2 * kc + 1][3]);
          }
          rs0 += e0 + e1 + f0 + f1;
          rs1 += e2 + e3 + f2 + f3;
          preg[s2][4 * kc + 0] = packh2(e0, e1);
          preg[s2][4 * kc + 1] = packh2(e2, e3);
          preg[s2][4 * kc + 2] = packh2(f0, f1);
          preg[s2][4 * kc + 3] = packh2(f2, f3);
        }
        lsum[s2][0] += rs0;
        lsum[s2][1] += rs1;
      }

      // ---- O += P V (V fragments shared across both slabs) ----
#pragma unroll
      for (int kc = 0; kc < 4; ++kc) {
#pragma unroll
        for (int dp = 0; dp < 8; ++dp) {
          uint32_t v0, v1, v2, v3;
          ldm_x4_t(v0, v1, v2, v3,
                   vs_base + v_off + kc * (16 * KSTR * 2) + dp * 32);
          mma16816(oacc[0][2 * dp], preg[0][4 * kc + 0], preg[0][4 * kc + 1],
                   preg[0][4 * kc + 2], preg[0][4 * kc + 3], v0, v1);
          mma16816(oacc[0][2 * dp + 1], preg[0][4 * kc + 0], preg[0][4 * kc + 1],
                   preg[0][4 * kc + 2], preg[0][4 * kc + 3], v2, v3);
          mma16816(oacc[1][2 * dp], preg[1][4 * kc + 0], preg[1][4 * kc + 1],
                   preg[1][4 * kc + 2], preg[1][4 * kc + 3], v0, v1);
          mma16816(oacc[1][2 * dp + 1], preg[1][4 * kc + 0], preg[1][4 * kc + 1],
                   preg[1][4 * kc + 2], preg[1][4 * kc + 3], v2, v3);
        }
      }
    }
    __syncthreads();
  }

  // ---- epilogue: normalize + store ----
#pragma unroll
  for (int s2 = 0; s2 < 2; s2++)
#pragma unroll
    for (int hf = 0; hf < 2; hf++) {
      float l = lsum[s2][hf];
      l += __shfl_xor_sync(0xffffffffu, l, 1);
      l += __shfl_xor_sync(0xffffffffu, l, 2);
      const float inv = 1.f / l;
      const int row = qw + s2 * 16 + hf * 8 + (lane >> 2);
      float* orow = out + ((size_t)(b * Ss + row) * Hh + h) * Dd;
#pragma unroll
      for (int dt = 0; dt < 16; ++dt) {
        int d = dt * 8 + ((lane & 3) << 1);
        float2 v = make_float2(oacc[s2][dt][2 * hf] * inv,
                               oacc[s2][dt][2 * hf + 1] * inv);
        *reinterpret_cast<float2*>(orow + d) = v;
      }
    }
}

extern "C" void kernel_launch(void* const* d_in, const int* in_sizes, int n_in,
                              void* d_out, int out_size) {
  (void)in_sizes; (void)n_in; (void)out_size;
  const float* qkv = (const float*)d_in[0];
  float* out = (float*)d_out;

  int nconv = Bb * Ss * 2 * Hh * (Dd / 4);
  convert_kv<<<(nconv + 255) / 256, 256>>>(qkv);

  cudaFuncSetAttribute(fa_fwd2,
                       cudaFuncAttributeMaxDynamicSharedMemorySize, SMEM_BYTES);
  fa_fwd2<<<Bb * Hh * NQT, NT, SMEM_BYTES>>>(qkv, out);
}

// round 11
// speedup vs baseline: 1.6291x; 1.2102x over previous
#include <cuda_runtime.h>
#include <cuda_fp16.h>
#include <cstdint>

namespace {

constexpr int Bb = 4, Ss = 2048, Hh = 16, Dd = 128;
constexpr int BM = 128;              // query rows per CTA
constexpr int BN = 64;               // keys per tile
constexpr int NT = 128;              // 4 warps, 32 query rows each
constexpr int KSTR = 136;            // smem row stride in halves (272B)
constexpr int NQT = Ss / BM;         // 16 query tiles per (b,h)
constexpr int TSTRIDE = 3 * Hh * Dd; // qkv token stride (floats)
constexpr int QBYTES = BM * KSTR * 2;        // 34816
constexpr int STAGEB = BN * KSTR * 2;        // 17408 per K or V stage
constexpr int SMEM_BYTES = QBYTES + 4 * STAGEB; // Q + 2x(K,V) = 104448
constexpr float SCALE2 = 0.08838834764831845f * 1.4426950408889634f; // 1/sqrt(d)*log2e
constexpr int KVN = Bb * Hh * Ss * Dd;       // 16.78M halves per tensor

__device__ __forceinline__ uint32_t cvta_s(const void* p) {
  return (uint32_t)__cvta_generic_to_shared(p);
}

__device__ __forceinline__ float ex2f(float x) {
  float y;
  asm("ex2.approx.f32 %0, %1;" : "=f"(y) : "f"(x));
  return y;
}

__device__ __forceinline__ void ldm_x4(uint32_t& r0, uint32_t& r1, uint32_t& r2,
                                       uint32_t& r3, uint32_t a) {
  asm volatile("ldmatrix.sync.aligned.m8n8.x4.shared.b16 {%0,%1,%2,%3}, [%4];"
               : "=r"(r0), "=r"(r1), "=r"(r2), "=r"(r3) : "r"(a));
}

__device__ __forceinline__ void ldm_x4_t(uint32_t& r0, uint32_t& r1, uint32_t& r2,
                                         uint32_t& r3, uint32_t a) {
  asm volatile("ldmatrix.sync.aligned.m8n8.x4.trans.shared.b16 {%0,%1,%2,%3}, [%4];"
               : "=r"(r0), "=r"(r1), "=r"(r2), "=r"(r3) : "r"(a));
}

__device__ __forceinline__ void mma16816(float* c, uint32_t a0, uint32_t a1,
                                         uint32_t a2, uint32_t a3,
                                         uint32_t b0, uint32_t b1) {
  asm volatile(
      "mma.sync.aligned.m16n8k16.row.col.f32.f16.f16.f32 "
      "{%0,%1,%2,%3}, {%4,%5,%6,%7}, {%8,%9}, {%0,%1,%2,%3};"
      : "+f"(c[0]), "+f"(c[1]), "+f"(c[2]), "+f"(c[3])
      : "r"(a0), "r"(a1), "r"(a2), "r"(a3), "r"(b0), "r"(b1));
}

__device__ __forceinline__ uint32_t packh2(float x, float y) {
  __half2 h = __floats2half2_rn(x, y);
  return *reinterpret_cast<uint32_t*>(&h);
}

__device__ __forceinline__ void cp16(uint32_t saddr, const void* gaddr) {
  asm volatile("cp.async.cg.shared.global [%0], [%1], 16;" ::
               "r"(saddr), "l"(gaddr));
}

#define CP_COMMIT() asm volatile("cp.async.commit_group;" ::: "memory")
#define CP_WAIT(N) asm volatile("cp.async.wait_group %0;" :: "n"(N) : "memory")

} // namespace

// fp16 K/V scratch, head-major [b][h][s][d]
__device__ __half g_Kh[KVN];
__device__ __half g_Vh[KVN];

// ---------------- prepass: fp32 [b,s,{K,V},h,d] -> fp16 [b,h,s,d] ----------------
__global__ void __launch_bounds__(256)
convert_kv(const float* __restrict__ qkv) {
  int i = blockIdx.x * 256 + threadIdx.x; // one float4 per thread
  if (i >= Bb * Ss * 2 * Hh * (Dd / 4)) return;
  int d4 = i & 31;
  int r = i >> 5;
  int h = r & (Hh - 1); r >>= 4;
  int c = r & 1;        r >>= 1;   // 0=K, 1=V
  int s = r & (Ss - 1);
  int b = r >> 11;
  const float4 f = *reinterpret_cast<const float4*>(
      qkv + (((size_t)(b * Ss + s) * 3 + (c + 1)) * Hh + h) * Dd + d4 * 4);
  uint2 v;
  v.x = packh2(f.x, f.y);
  v.y = packh2(f.z, f.w);
  __half* dst = (c ? g_Vh : g_Kh) + ((size_t)(b * Hh + h) * Ss + s) * Dd + d4 * 4;
  *reinterpret_cast<uint2*>(dst) = v;
}

// ---------------- main attention kernel ----------------
extern __shared__ char g_smem[];

__global__ void __launch_bounds__(NT, 2)
fa_fwd2(const float* __restrict__ qkv, float* __restrict__ out) {
  const uint32_t sb = cvta_s(g_smem);
  const int tid = threadIdx.x;
  const int w = tid >> 5;
  const int lane = tid & 31;

  // LPT ordering: heaviest q-tiles (qt = NQT-1, 16 KV tiles) launch first.
  const int bid = blockIdx.x;
  const int qt = NQT - 1 - (bid >> 6); // grid = 16 qt-groups x 64 (b,h)
  const int bh = bid & 63;
  const int b = bh >> 4;
  const int h = bh & (Hh - 1);
  const int q0 = qt * BM;

  const __half* kg = g_Kh + (size_t)bh * Ss * Dd;
  const __half* vg = g_Vh + (size_t)bh * Ss * Dd;
  const float* qbase = qkv + ((size_t)b * Ss + q0) * TSTRIDE + (size_t)h * Dd;

  const uint32_t qsb = sb;                 // Q: 128 x 136 halves
  const uint32_t st0 = sb + QBYTES;        // [K0][V0][K1][V1]

  const int ntiles = (q0 + BM) / BN;

  // ---- issue cp.async for K/V stage 0 ----
  {
    uint32_t ks = st0, vs = st0 + STAGEB;
#pragma unroll
    for (int j = 0; j < 8; ++j) {
      int idx = tid + j * NT;
      int row = idx >> 4, ch = idx & 15;
      uint32_t so = (uint32_t)(row * KSTR + ch * 8) * 2;
      cp16(ks + so, kg + (size_t)row * Dd + ch * 8);
      cp16(vs + so, vg + (size_t)row * Dd + ch * 8);
    }
    CP_COMMIT();
  }

  // ---- load Q (fp32 -> fp16, scale folded in) while stage0 is in flight ----
#pragma unroll 4
  for (int i = tid; i < BM * (Dd / 4); i += NT) {
    int row = i >> 5;
    int c = (i & 31) << 2;
    float4 f = *reinterpret_cast<const float4*>(qbase + (size_t)row * TSTRIDE + c);
    __half2* dq = reinterpret_cast<__half2*>(g_smem + (row * KSTR + c) * 2);
    dq[0] = __floats2half2_rn(f.x * SCALE2, f.y * SCALE2);
    dq[1] = __floats2half2_rn(f.z * SCALE2, f.w * SCALE2);
  }

  // ---- per-warp state ----
  float oacc[2][16][4];
#pragma unroll
  for (int s2 = 0; s2 < 2; s2++)
#pragma unroll
    for (int i = 0; i < 16; i++)
#pragma unroll
      for (int j = 0; j < 4; j++) oacc[s2][i][j] = 0.f;
  float lsum[2][2] = {{0.f, 0.f}, {0.f, 0.f}};

  const int qw = q0 + w * 32; // first query row of this warp (32 rows)

  const uint32_t a_off0 =
      ((uint32_t)((w * 32 + (lane & 15)) * KSTR + ((lane >> 4) << 3))) * 2u;
  const uint32_t a_off1 = a_off0 + (uint32_t)(16 * KSTR * 2);
  const uint32_t b_off =
      ((uint32_t)(((lane & 7) + ((lane >> 4) << 3)) * KSTR +
                  (((lane >> 3) & 1) << 3))) * 2u;
  const uint32_t v_off =
      ((uint32_t)(((lane & 7) + (((lane >> 3) & 1) << 3)) * KSTR +
                  ((lane >> 4) << 3))) * 2u;

  for (int t = 0; t < ntiles; ++t) {
    const int kv0 = t * BN;
    const bool hasnext = (t + 1) < ntiles;

    if (hasnext) { // prefetch stage t+1 into the other buffer
      uint32_t base = st0 + ((t + 1) & 1) * 2 * STAGEB;
      uint32_t ks = base, vs = base + STAGEB;
      const __half* kgn = kg + (size_t)(kv0 + BN) * Dd;
      const __half* vgn = vg + (size_t)(kv0 + BN) * Dd;
#pragma unroll
      for (int j = 0; j < 8; ++j) {
        int idx = tid + j * NT;
        int row = idx >> 4, ch = idx & 15;
        uint32_t so = (uint32_t)(row * KSTR + ch * 8) * 2;
        cp16(ks + so, kgn + (size_t)row * Dd + ch * 8);
        cp16(vs + so, vgn + (size_t)row * Dd + ch * 8);
      }
      CP_COMMIT();
      CP_WAIT(1); // stage t complete; t+1 still in flight
    } else {
      CP_WAIT(0);
    }
    __syncthreads();

    const uint32_t ks_base = st0 + (t & 1) * 2 * STAGEB;
    const uint32_t vs_base = ks_base + STAGEB;

    if (kv0 <= qw + 31) { // warp has unmasked keys in this tile
      // ---- S = Q K^T (two 16-row slabs) ----
      float sacc[2][8][4];
#pragma unroll
      for (int s2 = 0; s2 < 2; s2++)
#pragma unroll
        for (int i = 0; i < 8; i++)
#pragma unroll
          for (int j = 0; j < 4; j++) sacc[s2][i][j] = 0.f;

#pragma unroll
      for (int kk = 0; kk < 8; ++kk) {
        uint32_t a0[4], a1[4];
        ldm_x4(a0[0], a0[1], a0[2], a0[3], qsb + a_off0 + kk * 32);
        ldm_x4(a1[0], a1[1], a1[2], a1[3], qsb + a_off1 + kk * 32);
#pragma unroll
        for (int np = 0; np < 4; ++np) {
          uint32_t b0, b1, b2, b3;
          ldm_x4(b0, b1, b2, b3, ks_base + b_off + np * (16 * KSTR * 2) + kk * 32);
          mma16816(sacc[0][2 * np], a0[0], a0[1], a0[2], a0[3], b0, b1);
          mma16816(sacc[0][2 * np + 1], a0[0], a0[1], a0[2], a0[3], b2, b3);
          mma16816(sacc[1][2 * np], a1[0], a1[1], a1[2], a1[3], b0, b1);
          mma16816(sacc[1][2 * np + 1], a1[0], a1[1], a1[2], a1[3], b2, b3);
        }
      }

      // ---- interleaved: per kc-block, softmax+pack then immediately PV MMAs.
      //      exp2/sel of block kc+1 executes while block kc's MMAs drain. ----
      const bool needmask = (kv0 + BN - 1) > qw;
      const int rb0 = qw + (lane >> 2);
      const int rb1 = rb0 + 16;
#pragma unroll
      for (int kc = 0; kc < 4; ++kc) {
        uint32_t preg[2][4];
#pragma unroll
        for (int s2 = 0; s2 < 2; s2++) {
          const int rbase = (s2 == 0) ? rb0 : rb1;
          float e0, e1, e2, e3, f0, f1, f2, f3;
          if (needmask) {
            int na = kv0 + (2 * kc) * 8 + ((lane & 3) << 1);
            int nb = na + 8;
            e0 = (na > rbase) ? 0.f : ex2f(sacc[s2][2 * kc][0]);
            e1 = (na + 1 > rbase) ? 0.f : ex2f(sacc[s2][2 * kc][1]);
            e2 = (na > rbase + 8) ? 0.f : ex2f(sacc[s2][2 * kc][2]);
            e3 = (na + 1 > rbase + 8) ? 0.f : ex2f(sacc[s2][2 * kc][3]);
            f0 = (nb > rbase) ? 0.f : ex2f(sacc[s2][2 * kc + 1][0]);
            f1 = (nb + 1 > rbase) ? 0.f : ex2f(sacc[s2][2 * kc + 1][1]);
            f2 = (nb > rbase + 8) ? 0.f : ex2f(sacc[s2][2 * kc + 1][2]);
            f3 = (nb + 1 > rbase + 8) ? 0.f : ex2f(sacc[s2][2 * kc + 1][3]);
          } else {
            e0 = ex2f(sacc[s2][2 * kc][0]);
            e1 = ex2f(sacc[s2][2 * kc][1]);
            e2 = ex2f(sacc[s2][2 * kc][2]);
            e3 = ex2f(sacc[s2][2 * kc][3]);
            f0 = ex2f(sacc[s2][2 * kc + 1][0]);
            f1 = ex2f(sacc[s2][2 * kc + 1][1]);
            f2 = ex2f(sacc[s2][2 * kc + 1][2]);
            f3 = ex2f(sacc[s2][2 * kc + 1][3]);
          }
          lsum[s2][0] += e0 + e1 + f0 + f1;
          lsum[s2][1] += e2 + e3 + f2 + f3;
          preg[s2][0] = packh2(e0, e1);
          preg[s2][1] = packh2(e2, e3);
          preg[s2][2] = packh2(f0, f1);
          preg[s2][3] = packh2(f2, f3);
        }

        // PV MMAs for this kc-block (V fragments shared across both slabs)
#pragma unroll
        for (int dp = 0; dp < 8; ++dp) {
          uint32_t v0, v1, v2, v3;
          ldm_x4_t(v0, v1, v2, v3,
                   vs_base + v_off + kc * (16 * KSTR * 2) + dp * 32);
          mma16816(oacc[0][2 * dp], preg[0][0], preg[0][1], preg[0][2],
                   preg[0][3], v0, v1);
          mma16816(oacc[0][2 * dp + 1], preg[0][0], preg[0][1], preg[0][2],
                   preg[0][3], v2, v3);
          mma16816(oacc[1][2 * dp], preg[1][0], preg[1][1], preg[1][2],
                   preg[1][3], v0, v1);
          mma16816(oacc[1][2 * dp + 1], preg[1][0], preg[1][1], preg[1][2],
                   preg[1][3], v2, v3);
        }
      }
    }
    __syncthreads();
  }

  // ---- epilogue: normalize + store ----
#pragma unroll
  for (int s2 = 0; s2 < 2; s2++)
#pragma unroll
    for (int hf = 0; hf < 2; hf++) {
      float l = lsum[s2][hf];
      l += __shfl_xor_sync(0xffffffffu, l, 1);
      l += __shfl_xor_sync(0xffffffffu, l, 2);
      const float inv = 1.f / l;
      const int row = qw + s2 * 16 + hf * 8 + (lane >> 2);
      float* orow = out + ((size_t)(b * Ss + row) * Hh + h) * Dd;
#pragma unroll
      for (int dt = 0; dt < 16; ++dt) {
        int d = dt * 8 + ((lane & 3) << 1);
        float2 v = make_float2(oacc[s2][dt][2 * hf] * inv,
                               oacc[s2][dt][2 * hf + 1] * inv);
        *reinterpret_cast<float2*>(orow + d) = v;
      }
    }
}

extern "C" void kernel_launch(void* const* d_in, const int* in_sizes, int n_in,
                              void* d_out, int out_size) {
  (void)in_sizes; (void)n_in; (void)out_size;
  const float* qkv = (const float*)d_in[0];
  float* out = (float*)d_out;

  int nconv = Bb * Ss * 2 * Hh * (Dd / 4);
  convert_kv<<<(nconv + 255) / 256, 256>>>(qkv);

  cudaFuncSetAttribute(fa_fwd2,
                       cudaFuncAttributeMaxDynamicSharedMemorySize, SMEM_BYTES);
  fa_fwd2<<<Bb * Hh * NQT, NT, SMEM_BYTES>>>(qkv, out);
}

// round 13
// speedup vs baseline: 1.6346x; 1.0033x over previous
#include <cuda_runtime.h>
#include <cuda_fp16.h>
#include <cstdint>

namespace {

constexpr int Bb = 4, Ss = 2048, Hh = 16, Dd = 128;
constexpr int BM = 128;              // query rows per CTA
constexpr int BN = 64;               // keys per tile
constexpr int NT = 256;              // 8 warps, 16 query rows each
constexpr int KSTR = 136;            // smem row stride in halves (272B)
constexpr int NQT = Ss / BM;         // 16 query tiles per (b,h)
constexpr int TSTRIDE = 3 * Hh * Dd; // qkv token stride (floats)
constexpr int QBYTES = BM * KSTR * 2;        // 34816
constexpr int STAGEB = BN * KSTR * 2;        // 17408 per K or V stage
constexpr int SMEM_BYTES = QBYTES + 4 * STAGEB; // Q + 2x(K,V) = 104448
constexpr float SCALE2 = 0.08838834764831845f * 1.4426950408889634f; // 1/sqrt(d)*log2e
constexpr int KVN = Bb * Hh * Ss * Dd;       // 16.78M halves per tensor

__device__ __forceinline__ uint32_t cvta_s(const void* p) {
  return (uint32_t)__cvta_generic_to_shared(p);
}

// packed fp16x2 exp2 (one MUFU op for two values)
__device__ __forceinline__ uint32_t ex2x2(uint32_t x) {
  uint32_t y;
  asm("ex2.approx.f16x2 %0, %1;" : "=r"(y) : "r"(x));
  return y;
}

__device__ __forceinline__ void ldm_x4(uint32_t& r0, uint32_t& r1, uint32_t& r2,
                                       uint32_t& r3, uint32_t a) {
  asm volatile("ldmatrix.sync.aligned.m8n8.x4.shared.b16 {%0,%1,%2,%3}, [%4];"
               : "=r"(r0), "=r"(r1), "=r"(r2), "=r"(r3) : "r"(a));
}

__device__ __forceinline__ void ldm_x4_t(uint32_t& r0, uint32_t& r1, uint32_t& r2,
                                         uint32_t& r3, uint32_t a) {
  asm volatile("ldmatrix.sync.aligned.m8n8.x4.trans.shared.b16 {%0,%1,%2,%3}, [%4];"
               : "=r"(r0), "=r"(r1), "=r"(r2), "=r"(r3) : "r"(a));
}

__device__ __forceinline__ void mma16816(float* c, uint32_t a0, uint32_t a1,
                                         uint32_t a2, uint32_t a3,
                                         uint32_t b0, uint32_t b1) {
  asm volatile(
      "mma.sync.aligned.m16n8k16.row.col.f32.f16.f16.f32 "
      "{%0,%1,%2,%3}, {%4,%5,%6,%7}, {%8,%9}, {%0,%1,%2,%3};"
      : "+f"(c[0]), "+f"(c[1]), "+f"(c[2]), "+f"(c[3])
      : "r"(a0), "r"(a1), "r"(a2), "r"(a3), "r"(b0), "r"(b1));
}

__device__ __forceinline__ uint32_t packh2(float x, float y) {
  __half2 h = __floats2half2_rn(x, y);
  return *reinterpret_cast<uint32_t*>(&h);
}

__device__ __forceinline__ float h2sum(uint32_t a, uint32_t b) {
  __half2 s = __hadd2(*reinterpret_cast<__half2*>(&a),
                      *reinterpret_cast<__half2*>(&b));
  float2 f = __half22float2(s);
  return f.x + f.y;
}

__device__ __forceinline__ void cp16(uint32_t saddr, const void* gaddr) {
  asm volatile("cp.async.cg.shared.global [%0], [%1], 16;" ::
               "r"(saddr), "l"(gaddr));
}

#define CP_COMMIT() asm volatile("cp.async.commit_group;" ::: "memory")
#define CP_WAIT(N) asm volatile("cp.async.wait_group %0;" :: "n"(N) : "memory")

} // namespace

// fp16 K/V scratch, head-major [b][h][s][d]
__device__ __half g_Kh[KVN];
__device__ __half g_Vh[KVN];

// ---------------- prepass: fp32 [b,s,{K,V},h,d] -> fp16 [b,h,s,d] ----------------
__global__ void __launch_bounds__(256)
convert_kv(const float* __restrict__ qkv) {
  int i = blockIdx.x * 256 + threadIdx.x; // one float4 per thread
  if (i >= Bb * Ss * 2 * Hh * (Dd / 4)) return;
  int d4 = i & 31;
  int r = i >> 5;
  int h = r & (Hh - 1); r >>= 4;
  int c = r & 1;        r >>= 1;   // 0=K, 1=V
  int s = r & (Ss - 1);
  int b = r >> 11;
  const float4 f = *reinterpret_cast<const float4*>(
      qkv + (((size_t)(b * Ss + s) * 3 + (c + 1)) * Hh + h) * Dd + d4 * 4);
  uint2 v;
  v.x = packh2(f.x, f.y);
  v.y = packh2(f.z, f.w);
  __half* dst = (c ? g_Vh : g_Kh) + ((size_t)(b * Hh + h) * Ss + s) * Dd + d4 * 4;
  *reinterpret_cast<uint2*>(dst) = v;
}

// ---------------- main attention kernel ----------------
extern __shared__ char g_smem[];

__global__ void __launch_bounds__(NT, 2)
fa_fwd3(const float* __restrict__ qkv, float* __restrict__ out) {
  const uint32_t sb = cvta_s(g_smem);
  const int tid = threadIdx.x;
  const int w = tid >> 5;
  const int lane = tid & 31;

  // LPT ordering: heaviest q-tiles (qt = NQT-1) launch first.
  const int bid = blockIdx.x;
  const int qt = NQT - 1 - (bid >> 6); // grid = 16 qt-groups x 64 (b,h)
  const int bh = bid & 63;
  const int b = bh >> 4;
  const int h = bh & (Hh - 1);
  const int q0 = qt * BM;

  const __half* kg = g_Kh + (size_t)bh * Ss * Dd;
  const __half* vg = g_Vh + (size_t)bh * Ss * Dd;
  const float* qbase = qkv + ((size_t)b * Ss + q0) * TSTRIDE + (size_t)h * Dd;

  const uint32_t qsb = sb;                 // Q: 128 x 136 halves
  const uint32_t st0 = sb + QBYTES;        // [K0][V0][K1][V1]

  const int ntiles = (q0 + BM) / BN;

  // ---- issue cp.async for K/V stage 0 (4 x 16B per thread per tensor) ----
  {
    uint32_t ks = st0, vs = st0 + STAGEB;
#pragma unroll
    for (int j = 0; j < 4; ++j) {
      int idx = tid + j * NT;
      int row = idx >> 4, ch = idx & 15;
      uint32_t so = (uint32_t)(row * KSTR + ch * 8) * 2;
      cp16(ks + so, kg + (size_t)row * Dd + ch * 8);
      cp16(vs + so, vg + (size_t)row * Dd + ch * 8);
    }
    CP_COMMIT();
  }

  // ---- load Q (fp32 -> fp16, scale folded in) while stage0 is in flight ----
#pragma unroll 4
  for (int i = tid; i < BM * (Dd / 4); i += NT) {
    int row = i >> 5;
    int c = (i & 31) << 2;
    float4 f = *reinterpret_cast<const float4*>(qbase + (size_t)row * TSTRIDE + c);
    __half2* dq = reinterpret_cast<__half2*>(g_smem + (row * KSTR + c) * 2);
    dq[0] = __floats2half2_rn(f.x * SCALE2, f.y * SCALE2);
    dq[1] = __floats2half2_rn(f.z * SCALE2, f.w * SCALE2);
  }

  // ---- per-warp state (16 rows/warp) ----
  float oacc[16][4];
#pragma unroll
  for (int i = 0; i < 16; i++)
#pragma unroll
    for (int j = 0; j < 4; j++) oacc[i][j] = 0.f;
  float lsum[2] = {0.f, 0.f}; // rows r, r+8

  const int qw = q0 + w * 16; // first query row of this warp

  const uint32_t a_off =
      ((uint32_t)((w * 16 + (lane & 15)) * KSTR + ((lane >> 4) << 3))) * 2u;
  const uint32_t b_off =
      ((uint32_t)(((lane & 7) + ((lane >> 4) << 3)) * KSTR +
                  (((lane >> 3) & 1) << 3))) * 2u;
  const uint32_t v_off =
      ((uint32_t)(((lane & 7) + (((lane >> 3) & 1) << 3)) * KSTR +
                  ((lane >> 4) << 3))) * 2u;

  for (int t = 0; t < ntiles; ++t) {
    const int kv0 = t * BN;
    const bool hasnext = (t + 1) < ntiles;

    if (hasnext) { // prefetch stage t+1 into the other buffer
      uint32_t base = st0 + ((t + 1) & 1) * 2 * STAGEB;
      uint32_t ks = base, vs = base + STAGEB;
      const __half* kgn = kg + (size_t)(kv0 + BN) * Dd;
      const __half* vgn = vg + (size_t)(kv0 + BN) * Dd;
#pragma unroll
      for (int j = 0; j < 4; ++j) {
        int idx = tid + j * NT;
        int row = idx >> 4, ch = idx & 15;
        uint32_t so = (uint32_t)(row * KSTR + ch * 8) * 2;
        cp16(ks + so, kgn + (size_t)row * Dd + ch * 8);
        cp16(vs + so, vgn + (size_t)row * Dd + ch * 8);
      }
      CP_COMMIT();
      CP_WAIT(1); // stage t complete; t+1 still in flight
    } else {
      CP_WAIT(0);
    }
    __syncthreads();

    const uint32_t ks_base = st0 + (t & 1) * 2 * STAGEB;
    const uint32_t vs_base = ks_base + STAGEB;

    if (kv0 <= qw + 15) { // warp has unmasked keys in this tile
      // ---- S = Q K^T ----
      float sacc[8][4];
#pragma unroll
      for (int i = 0; i < 8; i++)
#pragma unroll
        for (int j = 0; j < 4; j++) sacc[i][j] = 0.f;

#pragma unroll
      for (int kk = 0; kk < 8; ++kk) {
        uint32_t a0, a1, a2, a3;
        ldm_x4(a0, a1, a2, a3, qsb + a_off + kk * 32);
#pragma unroll
        for (int np = 0; np < 4; ++np) {
          uint32_t b0, b1, b2, b3;
          ldm_x4(b0, b1, b2, b3, ks_base + b_off + np * (16 * KSTR * 2) + kk * 32);
          mma16816(sacc[2 * np], a0, a1, a2, a3, b0, b1);
          mma16816(sacc[2 * np + 1], a0, a1, a2, a3, b2, b3);
        }
      }

      // ---- per-kc: fp16x2 exp2 + mask -> PV MMAs (interleaved) ----
      const bool needmask = (kv0 + BN - 1) > qw;
      const int rb0 = qw + (lane >> 2);
#pragma unroll
      for (int kc = 0; kc < 4; ++kc) {
        float e0 = sacc[2 * kc][0], e1 = sacc[2 * kc][1];
        float e2 = sacc[2 * kc][2], e3 = sacc[2 * kc][3];
        float f0 = sacc[2 * kc + 1][0], f1 = sacc[2 * kc + 1][1];
        float f2 = sacc[2 * kc + 1][2], f3 = sacc[2 * kc + 1][3];
        if (needmask) {
          int na = kv0 + (2 * kc) * 8 + ((lane & 3) << 1);
          int nb = na + 8;
          e0 = (na > rb0) ? -100.f : e0;
          e1 = (na + 1 > rb0) ? -100.f : e1;
          e2 = (na > rb0 + 8) ? -100.f : e2;
          e3 = (na + 1 > rb0 + 8) ? -100.f : e3;
          f0 = (nb > rb0) ? -100.f : f0;
          f1 = (nb + 1 > rb0) ? -100.f : f1;
          f2 = (nb > rb0 + 8) ? -100.f : f2;
          f3 = (nb + 1 > rb0 + 8) ? -100.f : f3;
        }
        uint32_t preg0 = ex2x2(packh2(e0, e1)); // row r,   cols n..n+1
        uint32_t preg1 = ex2x2(packh2(e2, e3)); // row r+8
        uint32_t preg2 = ex2x2(packh2(f0, f1)); // row r,   cols n+8..n+9
        uint32_t preg3 = ex2x2(packh2(f2, f3)); // row r+8
        lsum[0] += h2sum(preg0, preg2);
        lsum[1] += h2sum(preg1, preg3);

        // PV MMAs for this kc-block
#pragma unroll
        for (int dp = 0; dp < 8; ++dp) {
          uint32_t v0, v1, v2, v3;
          ldm_x4_t(v0, v1, v2, v3,
                   vs_base + v_off + kc * (16 * KSTR * 2) + dp * 32);
          mma16816(oacc[2 * dp], preg0, preg1, preg2, preg3, v0, v1);
          mma16816(oacc[2 * dp + 1], preg0, preg1, preg2, preg3, v2, v3);
        }
      }
    }
    __syncthreads();
  }

  // ---- epilogue: normalize + store ----
#pragma unroll
  for (int hf = 0; hf < 2; hf++) {
    float l = lsum[hf];
    l += __shfl_xor_sync(0xffffffffu, l, 1);
    l += __shfl_xor_sync(0xffffffffu, l, 2);
    const float inv = 1.f / l;
    const int row = qw + hf * 8 + (lane >> 2);
    float* orow = out + ((size_t)(b * Ss + row) * Hh + h) * Dd;
#pragma unroll
    for (int dt = 0; dt < 16; ++dt) {
      int d = dt * 8 + ((lane & 3) << 1);
      float2 v = make_float2(oacc[dt][2 * hf] * inv, oacc[dt][2 * hf + 1] * inv);
      *reinterpret_cast<float2*>(orow + d) = v;
    }
  }
}

extern "C" void kernel_launch(void* const* d_in, const int* in_sizes, int n_in,
                              void* d_out, int out_size) {
  (void)in_sizes; (void)n_in; (void)out_size;
  const float* qkv = (const float*)d_in[0];
  float* out = (float*)d_out;

  int nconv = Bb * Ss * 2 * Hh * (Dd / 4);
  convert_kv<<<(nconv + 255) / 256, 256>>>(qkv);

  cudaFuncSetAttribute(fa_fwd3,
                       cudaFuncAttributeMaxDynamicSharedMemorySize, SMEM_BYTES);
  fa_fwd3<<<Bb * Hh * NQT, NT, SMEM_BYTES>>>(qkv, out);
}